// round 3
// baseline (speedup 1.0000x reference)
#include <cuda_runtime.h>
#include <cuda_bf16.h>
#include <cstdint>

#define CDIM 768
#define MTOK 104          // padded token count
#define MT_REAL 100
#define KP2 120           // padded m dim for t1T
#define MTILE 128
#define XS_STRIDE 776     // bf16 elems per Xs row (padded: 768+8)
#define TS_STRIDE 72      // padded k-chunk stride for tokens stage
#define BS2_STRIDE 120    // m stride for t1T stage
#define BS3_STRIDE 72     // padded k stride for w2 stage
#define SMEM_BYTES (MTILE*XS_STRIDE*2 + 18432)

__device__ __align__(16) float g_tokens[MT_REAL * CDIM];
__device__ __align__(16) __nv_bfloat16 g_tokens_bf[MTOK * CDIM];
__device__ __align__(16) __nv_bfloat16 g_t1T[CDIM * KP2];
__device__ __align__(16) __nv_bfloat16 g_w2bf[CDIM * CDIM];

__device__ __forceinline__ uint32_t pack_bf2(float a, float b) {
    __nv_bfloat162 h = __floats2bfloat162_rn(a, b);
    return *reinterpret_cast<uint32_t*>(&h);
}

__device__ __forceinline__ void mma16816(float* d, const uint32_t* a, const uint32_t* b) {
    asm volatile(
        "mma.sync.aligned.m16n8k16.row.col.f32.bf16.bf16.f32 "
        "{%0,%1,%2,%3}, {%4,%5,%6,%7}, {%8,%9}, {%0,%1,%2,%3};"
        : "+f"(d[0]), "+f"(d[1]), "+f"(d[2]), "+f"(d[3])
        : "r"(a[0]), "r"(a[1]), "r"(a[2]), "r"(a[3]), "r"(b[0]), "r"(b[1]));
}

__device__ __forceinline__ void cp_async16(void* dst_smem, const void* src) {
    uint32_t d = (uint32_t)__cvta_generic_to_shared(dst_smem);
    asm volatile("cp.async.cg.shared.global [%0], [%1], 16;\n" :: "r"(d), "l"(src));
}
#define CP_COMMIT() asm volatile("cp.async.commit_group;\n" ::: "memory")
#define CP_WAIT0()  asm volatile("cp.async.wait_group 0;\n" ::: "memory")

// ---------------- prep kernels ----------------

__global__ void prep_tokens(const float* __restrict__ ta, const float* __restrict__ tb,
                            const int* __restrict__ layer_p) {
    int L = __ldg(layer_p);
    int i = blockIdx.x * 256 + threadIdx.x;
    if (i >= MTOK * CDIM) return;
    int m = i / CDIM, c = i % CDIM;
    float acc = 0.f;
    if (m < MT_REAL) {
        const float* a = ta + (size_t)L * MT_REAL * 32 + m * 32;
        const float* b = tb + (size_t)L * 32 * CDIM + c;
#pragma unroll
        for (int k = 0; k < 32; k++) acc += __ldg(a + k) * __ldg(b + k * CDIM);
        g_tokens[m * CDIM + c] = acc;
    }
    g_tokens_bf[i] = __float2bfloat16(acc);
}

__global__ void prep_t1(const float* __restrict__ w1, const float* __restrict__ b1) {
    __shared__ float w1row[CDIM];
    int c = blockIdx.x;
    for (int k = threadIdx.x; k < CDIM; k += blockDim.x) w1row[k] = w1[(size_t)c * CDIM + k];
    __syncthreads();
    int m = threadIdx.x;
    if (m >= KP2) return;
    float acc = 0.f;
    if (m >= 1 && m < MT_REAL) {
        const float* tok = g_tokens + (size_t)m * CDIM;
#pragma unroll 8
        for (int k = 0; k < CDIM; k++) acc += tok[k] * w1row[k];
        acc += __ldg(b1 + c);
    }
    g_t1T[(size_t)c * KP2 + m] = __float2bfloat16(acc);
}

__global__ void prep_w2(const float* __restrict__ w2) {
    int i = blockIdx.x * 256 + threadIdx.x;
    if (i < CDIM * CDIM) g_w2bf[i] = __float2bfloat16(__ldg(w2 + i));
}

__global__ void copy_cls(const float* __restrict__ feats, float* __restrict__ out) {
    int i = blockIdx.x * 256 + threadIdx.x;
    if (i < 64 * CDIM / 4) ((float4*)out)[i] = ((const float4*)feats)[i];
}

// ---------------- fused main kernel ----------------

__global__ __launch_bounds__(256, 1) void lst_main(
    const float* __restrict__ feats, const float* __restrict__ b2p,
    const float* __restrict__ scale_p, float* __restrict__ out) {
    extern __shared__ __align__(16) char smem_raw[];
    __nv_bfloat16* Xs = (__nv_bfloat16*)smem_raw;
    uint32_t* Xu = (uint32_t*)Xs;
    uint32_t* Su = (uint32_t*)(Xs + MTILE * XS_STRIDE);

    const int tid = threadIdx.x;
    const int w = tid >> 5, lane = tid & 31;
    const int g = lane >> 2, tg = lane & 3;
    const int wr0 = w * 16;
    const int row0 = blockIdx.x * MTILE;
    const float* xg = feats + 64 * CDIM + (size_t)row0 * CDIM;

    // ---- Phase 0: x tile -> bf16 smem ----
    for (int i = tid; i < MTILE * (CDIM / 4); i += 256) {
        int r = i / (CDIM / 4);
        int c4 = i % (CDIM / 4);
        float4 v = __ldg(&((const float4*)xg)[(size_t)r * (CDIM / 4) + c4]);
        Xu[r * (XS_STRIDE / 2) + c4 * 2] = pack_bf2(v.x, v.y);
        Xu[r * (XS_STRIDE / 2) + c4 * 2 + 1] = pack_bf2(v.z, v.w);
    }
    __syncthreads();

    // ---- Phase 1: GEMM1 logits = X @ tokens^T ----
    float acc1[13][4];
#pragma unroll
    for (int t = 0; t < 13; t++)
#pragma unroll
        for (int j = 0; j < 4; j++) acc1[t][j] = 0.f;

    const uint32_t* gtok = (const uint32_t*)g_tokens_bf;
    for (int kc = 0; kc < 12; kc++) {
        for (int i = tid; i < MTOK * 32; i += 256) {
            int r = i >> 5, cp = i & 31;
            Su[r * (TS_STRIDE / 2) + cp] = __ldg(&gtok[r * (CDIM / 2) + kc * 32 + cp]);
        }
        __syncthreads();
#pragma unroll
        for (int ks = 0; ks < 4; ks++) {
            int kg = kc * 64 + ks * 16;
            uint32_t a[4];
            a[0] = Xu[(wr0 + g) * (XS_STRIDE / 2) + kg / 2 + tg];
            a[1] = Xu[(wr0 + g + 8) * (XS_STRIDE / 2) + kg / 2 + tg];
            a[2] = Xu[(wr0 + g) * (XS_STRIDE / 2) + kg / 2 + 4 + tg];
            a[3] = Xu[(wr0 + g + 8) * (XS_STRIDE / 2) + kg / 2 + 4 + tg];
#pragma unroll
            for (int t = 0; t < 13; t++) {
                uint32_t b[2];
                b[0] = Su[(t * 8 + g) * (TS_STRIDE / 2) + ks * 8 + tg];
                b[1] = Su[(t * 8 + g) * (TS_STRIDE / 2) + ks * 8 + 4 + tg];
                mma16816(acc1[t], a, b);
            }
        }
        __syncthreads();
    }

    // ---- Phase 1.5: softmax in registers ----
    const float rsc = 0.03608439182435161f; // 768^-0.5
    float mx0 = -1e30f, mx1 = -1e30f;
#pragma unroll
    for (int t = 0; t < 13; t++)
#pragma unroll
        for (int j = 0; j < 4; j++) {
            int m = t * 8 + tg * 2 + (j & 1);
            float v = acc1[t][j] * rsc;
            acc1[t][j] = v;
            if (m < MT_REAL) { if (j < 2) mx0 = fmaxf(mx0, v); else mx1 = fmaxf(mx1, v); }
        }
    mx0 = fmaxf(mx0, __shfl_xor_sync(0xffffffffu, mx0, 1));
    mx0 = fmaxf(mx0, __shfl_xor_sync(0xffffffffu, mx0, 2));
    mx1 = fmaxf(mx1, __shfl_xor_sync(0xffffffffu, mx1, 1));
    mx1 = fmaxf(mx1, __shfl_xor_sync(0xffffffffu, mx1, 2));
    float s0 = 0.f, s1 = 0.f;
#pragma unroll
    for (int t = 0; t < 13; t++)
#pragma unroll
        for (int j = 0; j < 4; j++) {
            int m = t * 8 + tg * 2 + (j & 1);
            float e = (m < MT_REAL) ? __expf(acc1[t][j] - ((j < 2) ? mx0 : mx1)) : 0.f;
            acc1[t][j] = e;
            if (j < 2) s0 += e; else s1 += e;
        }
    s0 += __shfl_xor_sync(0xffffffffu, s0, 1);
    s0 += __shfl_xor_sync(0xffffffffu, s0, 2);
    s1 += __shfl_xor_sync(0xffffffffu, s1, 1);
    s1 += __shfl_xor_sync(0xffffffffu, s1, 2);
    float inv0 = 1.f / s0, inv1 = 1.f / s1;
    if (tg == 0) { acc1[0][0] = 0.f; acc1[0][2] = 0.f; }  // drop token m=0

    // pack probabilities directly into GEMM2 A-fragments (K = m, 7 chunks of 16)
    uint32_t pa[7][4];
#pragma unroll
    for (int q = 0; q < 7; q++) {
        int t0 = 2 * q;
        pa[q][0] = pack_bf2(acc1[t0][0] * inv0, acc1[t0][1] * inv0);
        pa[q][1] = pack_bf2(acc1[t0][2] * inv1, acc1[t0][3] * inv1);
        if (t0 + 1 < 13) {
            pa[q][2] = pack_bf2(acc1[t0 + 1][0] * inv0, acc1[t0 + 1][1] * inv0);
            pa[q][3] = pack_bf2(acc1[t0 + 1][2] * inv1, acc1[t0 + 1][3] * inv1);
        } else { pa[q][2] = 0u; pa[q][3] = 0u; }
    }

    // ---- Phase 2: delta1 = P @ t1full, y = x + delta1 (in place over Xs) ----
    const uint32_t* gt1 = (const uint32_t*)g_t1T;
    for (int nc = 0; nc < 12; nc++) {
        __syncthreads();
        for (int i = tid; i < 64 * (KP2 / 2); i += 256) {
            int r = i / (KP2 / 2), col = i % (KP2 / 2);
            Su[r * (BS2_STRIDE / 2) + col] = __ldg(&gt1[(size_t)(nc * 64 + r) * (KP2 / 2) + col]);
        }
        __syncthreads();
        float acc2[8][4];
#pragma unroll
        for (int t = 0; t < 8; t++)
#pragma unroll
            for (int j = 0; j < 4; j++) acc2[t][j] = 0.f;
#pragma unroll
        for (int q = 0; q < 7; q++) {
#pragma unroll
            for (int t = 0; t < 8; t++) {
                uint32_t b[2];
                b[0] = Su[(t * 8 + g) * (BS2_STRIDE / 2) + q * 8 + tg];
                b[1] = Su[(t * 8 + g) * (BS2_STRIDE / 2) + q * 8 + 4 + tg];
                mma16816(acc2[t], pa[q], b);
            }
        }
#pragma unroll
        for (int t = 0; t < 8; t++) {
            int c0 = nc * 64 + t * 8 + tg * 2;
            uint32_t* p0 = &Xu[(wr0 + g) * (XS_STRIDE / 2) + c0 / 2];
            uint32_t* p1 = &Xu[(wr0 + g + 8) * (XS_STRIDE / 2) + c0 / 2];
            __nv_bfloat162 x0 = *(__nv_bfloat162*)p0;
            __nv_bfloat162 x1 = *(__nv_bfloat162*)p1;
            *p0 = pack_bf2(__bfloat162float(x0.x) + acc2[t][0],
                           __bfloat162float(x0.y) + acc2[t][1]);
            *p1 = pack_bf2(__bfloat162float(x1.x) + acc2[t][2],
                           __bfloat162float(x1.y) + acc2[t][3]);
        }
    }

    // ---- Phase 3: out = x + scale * (Y @ w2^T + b2) ----
    const float scale = __ldg(scale_p);
    const float2* b2v = (const float2*)b2p;
    const float2* xg2 = (const float2*)xg;
    float2* outg2 = (float2*)(out + 64 * CDIM + (size_t)row0 * CDIM);
    uint32_t* B0 = Su;
    uint32_t* B1 = Su + 64 * (BS3_STRIDE / 2);
    const __nv_bfloat16* w2b = g_w2bf;

    for (int nc = 0; nc < 12; nc++) {
        __syncthreads();
        float acc3[8][4];
#pragma unroll
        for (int t = 0; t < 8; t++)
#pragma unroll
            for (int j = 0; j < 4; j++) acc3[t][j] = 0.f;

        // prologue: chunk kc=0 into B0
#pragma unroll
        for (int i = 0; i < 2; i++) {
            int e = tid + i * 256;
            int r = e >> 3, s = e & 7;
            cp_async16((char*)(B0 + r * (BS3_STRIDE / 2) + s * 4),
                       w2b + (size_t)(nc * 64 + r) * CDIM + s * 8);
        }
        CP_COMMIT();

        for (int kc = 0; kc < 12; kc++) {
            CP_WAIT0();
            __syncthreads();
            uint32_t* Bcur = (kc & 1) ? B1 : B0;
            if (kc < 11) {
                uint32_t* Bnext = (kc & 1) ? B0 : B1;
#pragma unroll
                for (int i = 0; i < 2; i++) {
                    int e = tid + i * 256;
                    int r = e >> 3, s = e & 7;
                    cp_async16((char*)(Bnext + r * (BS3_STRIDE / 2) + s * 4),
                               w2b + (size_t)(nc * 64 + r) * CDIM + (kc + 1) * 64 + s * 8);
                }
                CP_COMMIT();
            }
#pragma unroll
            for (int ks = 0; ks < 4; ks++) {
                int kg = kc * 64 + ks * 16;
                uint32_t a[4];
                a[0] = Xu[(wr0 + g) * (XS_STRIDE / 2) + kg / 2 + tg];
                a[1] = Xu[(wr0 + g + 8) * (XS_STRIDE / 2) + kg / 2 + tg];
                a[2] = Xu[(wr0 + g) * (XS_STRIDE / 2) + kg / 2 + 4 + tg];
                a[3] = Xu[(wr0 + g + 8) * (XS_STRIDE / 2) + kg / 2 + 4 + tg];
#pragma unroll
                for (int t = 0; t < 8; t++) {
                    uint32_t b[2];
                    b[0] = Bcur[(t * 8 + g) * (BS3_STRIDE / 2) + ks * 8 + tg];
                    b[1] = Bcur[(t * 8 + g) * (BS3_STRIDE / 2) + ks * 8 + 4 + tg];
                    mma16816(acc3[t], a, b);
                }
            }
        }
        // epilogue: fp32 x re-read + scaled update
#pragma unroll
        for (int t = 0; t < 8; t++) {
            int n = nc * 64 + t * 8 + tg * 2;
            float2 bb = __ldg(&b2v[n >> 1]);
            int r1 = wr0 + g, r2 = r1 + 8;
            float2 x1 = __ldg(&xg2[(size_t)r1 * (CDIM / 2) + (n >> 1)]);
            float2 x2 = __ldg(&xg2[(size_t)r2 * (CDIM / 2) + (n >> 1)]);
            float2 o1, o2;
            o1.x = x1.x + scale * (acc3[t][0] + bb.x);
            o1.y = x1.y + scale * (acc3[t][1] + bb.y);
            o2.x = x2.x + scale * (acc3[t][2] + bb.x);
            o2.y = x2.y + scale * (acc3[t][3] + bb.y);
            outg2[(size_t)r1 * (CDIM / 2) + (n >> 1)] = o1;
            outg2[(size_t)r2 * (CDIM / 2) + (n >> 1)] = o2;
        }
    }
}

// ---------------- launch ----------------

extern "C" void kernel_launch(void* const* d_in, const int* in_sizes, int n_in,
                              void* d_out, int out_size) {
    (void)in_sizes; (void)n_in; (void)out_size;
    const float* feats = (const float*)d_in[0];
    const float* ta    = (const float*)d_in[1];
    const float* tb    = (const float*)d_in[2];
    const float* scale = (const float*)d_in[3];
    const float* w1    = (const float*)d_in[4];
    const float* b1    = (const float*)d_in[5];
    const float* w2    = (const float*)d_in[6];
    const float* b2    = (const float*)d_in[7];
    const int*   layer = (const int*)d_in[8];
    float* out = (float*)d_out;

    prep_tokens<<<(MTOK * CDIM + 255) / 256, 256>>>(ta, tb, layer);
    prep_t1<<<CDIM, 128>>>(w1, b1);
    prep_w2<<<(CDIM * CDIM + 255) / 256, 256>>>(w2);
    copy_cls<<<(64 * CDIM / 4 + 255) / 256, 256>>>(feats, out);

    static bool attr_set = false;
    if (!attr_set) {
        cudaFuncSetAttribute(lst_main, cudaFuncAttributeMaxDynamicSharedMemorySize, SMEM_BYTES);
        attr_set = true;
    }
    lst_main<<<65536 / MTILE, 256, SMEM_BYTES>>>(feats, b2, scale, out);
}

// round 4
// speedup vs baseline: 1.2718x; 1.2718x over previous
#include <cuda_runtime.h>
#include <cuda_bf16.h>
#include <cstdint>

#define CDIM 768
#define MTOK 104          // padded token count
#define MT_REAL 100
#define KP2 120           // padded m dim for t1T (bf16 elems; 240B row)
#define MTILE 128
#define XS_STRIDE 776     // bf16 elems per Xs row (768+8 pad); 1552 B
#define XS_ROWB 1552
#define TS_ROWB 144       // tokens stage row bytes (128 data + 16 pad)
#define S2_ROWB 240       // t1T stage row bytes
#define B3_ROWB 144       // w2 stage row bytes
#define TS_BUF_B (MTOK*TS_ROWB)        // 14976
#define B3_BUF_B (64*B3_ROWB)          // 9216
#define SMEM_BYTES (MTILE*XS_ROWB + 2*TS_BUF_B)   // 198656 + 29952 = 228608

__device__ __align__(16) float g_tokens[MT_REAL * CDIM];
__device__ __align__(16) __nv_bfloat16 g_tokens_bf[MTOK * CDIM];
__device__ __align__(16) __nv_bfloat16 g_t1T[CDIM * KP2];
__device__ __align__(16) __nv_bfloat16 g_w2bf[CDIM * CDIM];

__device__ __forceinline__ uint32_t pack_bf2(float a, float b) {
    __nv_bfloat162 h = __floats2bfloat162_rn(a, b);
    return *reinterpret_cast<uint32_t*>(&h);
}

__device__ __forceinline__ void mma16816(float* d, const uint32_t* a, const uint32_t* b) {
    asm volatile(
        "mma.sync.aligned.m16n8k16.row.col.f32.bf16.bf16.f32 "
        "{%0,%1,%2,%3}, {%4,%5,%6,%7}, {%8,%9}, {%0,%1,%2,%3};"
        : "+f"(d[0]), "+f"(d[1]), "+f"(d[2]), "+f"(d[3])
        : "r"(a[0]), "r"(a[1]), "r"(a[2]), "r"(a[3]), "r"(b[0]), "r"(b[1]));
}

__device__ __forceinline__ void ldsm_x4(uint32_t& r0, uint32_t& r1, uint32_t& r2, uint32_t& r3,
                                        uint32_t addr) {
    asm volatile("ldmatrix.sync.aligned.m8n8.x4.shared.b16 {%0,%1,%2,%3}, [%4];"
                 : "=r"(r0), "=r"(r1), "=r"(r2), "=r"(r3) : "r"(addr));
}
__device__ __forceinline__ void ldsm_x2(uint32_t& r0, uint32_t& r1, uint32_t addr) {
    asm volatile("ldmatrix.sync.aligned.m8n8.x2.shared.b16 {%0,%1}, [%2];"
                 : "=r"(r0), "=r"(r1) : "r"(addr));
}

__device__ __forceinline__ void cp_async16(uint32_t dst_smem, const void* src) {
    asm volatile("cp.async.cg.shared.global [%0], [%1], 16;\n" :: "r"(dst_smem), "l"(src));
}
#define CP_COMMIT() asm volatile("cp.async.commit_group;\n" ::: "memory")
#define CP_WAIT0()  asm volatile("cp.async.wait_group 0;\n" ::: "memory")

// ---------------- prep kernels ----------------

__global__ void prep_tokens(const float* __restrict__ ta, const float* __restrict__ tb,
                            const int* __restrict__ layer_p) {
    int L = __ldg(layer_p);
    int i = blockIdx.x * 256 + threadIdx.x;
    if (i >= MTOK * CDIM) return;
    int m = i / CDIM, c = i % CDIM;
    float acc = 0.f;
    if (m < MT_REAL) {
        const float* a = ta + (size_t)L * MT_REAL * 32 + m * 32;
        const float* b = tb + (size_t)L * 32 * CDIM + c;
#pragma unroll
        for (int k = 0; k < 32; k++) acc += __ldg(a + k) * __ldg(b + k * CDIM);
        g_tokens[m * CDIM + c] = acc;
    }
    g_tokens_bf[i] = __float2bfloat16(acc);
}

#define T1_CBLK 8
__global__ void prep_t1(const float* __restrict__ w1, const float* __restrict__ b1) {
    __shared__ float w1s[T1_CBLK][CDIM];
    int c0 = blockIdx.x * T1_CBLK;
    for (int i = threadIdx.x; i < T1_CBLK * CDIM; i += blockDim.x)
        w1s[i / CDIM][i % CDIM] = __ldg(&w1[(size_t)(c0 + i / CDIM) * CDIM + (i % CDIM)]);
    __syncthreads();
    int m = threadIdx.x;
    if (m >= KP2) return;
    float acc[T1_CBLK];
#pragma unroll
    for (int j = 0; j < T1_CBLK; j++) acc[j] = 0.f;
    bool live = (m >= 1 && m < MT_REAL);
    if (live) {
        const float* tok = g_tokens + (size_t)m * CDIM;
#pragma unroll 4
        for (int k = 0; k < CDIM; k++) {
            float tv = tok[k];
#pragma unroll
            for (int j = 0; j < T1_CBLK; j++) acc[j] += tv * w1s[j][k];
        }
    }
#pragma unroll
    for (int j = 0; j < T1_CBLK; j++) {
        float v = live ? (acc[j] + __ldg(b1 + c0 + j)) : 0.f;
        g_t1T[(size_t)(c0 + j) * KP2 + m] = __float2bfloat16(v);
    }
}

__global__ void prep_w2(const float* __restrict__ w2) {
    int i = blockIdx.x * 256 + threadIdx.x;
    if (i < CDIM * CDIM) g_w2bf[i] = __float2bfloat16(__ldg(w2 + i));
}

__global__ void copy_cls(const float* __restrict__ feats, float* __restrict__ out) {
    int i = blockIdx.x * 256 + threadIdx.x;
    if (i < 64 * CDIM / 4) ((float4*)out)[i] = ((const float4*)feats)[i];
}

// ---------------- fused main kernel ----------------

__global__ __launch_bounds__(256, 1) void lst_main(
    const float* __restrict__ feats, const float* __restrict__ b2p,
    const float* __restrict__ scale_p, float* __restrict__ out) {
    extern __shared__ __align__(16) char smem_raw[];
    __nv_bfloat16* Xs = (__nv_bfloat16*)smem_raw;
    uint32_t* Xu = (uint32_t*)Xs;
    char* Sbase = smem_raw + MTILE * XS_ROWB;

    const uint32_t xs_u = (uint32_t)__cvta_generic_to_shared(smem_raw);
    const uint32_t s_u  = (uint32_t)__cvta_generic_to_shared(Sbase);

    const int tid = threadIdx.x;
    const int w = tid >> 5, lane = tid & 31;
    const int g = lane >> 2, tg = lane & 3;
    const int wr0 = w * 16;
    const int p = lane >> 3, lr = lane & 7;
    const int row0 = blockIdx.x * MTILE;
    const float* xg = feats + 64 * CDIM + (size_t)row0 * CDIM;

    // per-lane ldmatrix address bases
    const uint32_t aA_base = xs_u + (wr0 + ((p & 1) << 3) + lr) * XS_ROWB + ((p >> 1) << 4);
    const uint32_t bL_off144 = (uint32_t)((((p >> 1) << 3) + lr) * TS_ROWB + ((p & 1) << 4));
    const uint32_t bL_off240 = (uint32_t)((((p >> 1) << 3) + lr) * S2_ROWB + ((p & 1) << 4));

    // ---- prologue: issue tokens chunk kc=0 into T0 ----
    const char* gtokc = (const char*)g_tokens_bf;
    for (int i = tid; i < MTOK * 8; i += 256) {
        int r = i >> 3, s = i & 7;
        cp_async16(s_u + r * TS_ROWB + s * 16, gtokc + r * (CDIM * 2) + s * 16);
    }
    CP_COMMIT();

    // ---- Phase 0: x tile -> bf16 smem ----
    for (int i = tid; i < MTILE * (CDIM / 4); i += 256) {
        int r = i / (CDIM / 4);
        int c4 = i % (CDIM / 4);
        float4 v = __ldg(&((const float4*)xg)[(size_t)r * (CDIM / 4) + c4]);
        Xu[r * (XS_STRIDE / 2) + c4 * 2] = pack_bf2(v.x, v.y);
        Xu[r * (XS_STRIDE / 2) + c4 * 2 + 1] = pack_bf2(v.z, v.w);
    }

    // ---- Phase 1: GEMM1 logits = X @ tokens^T ----
    float acc1[13][4];
#pragma unroll
    for (int t = 0; t < 13; t++)
#pragma unroll
        for (int j = 0; j < 4; j++) acc1[t][j] = 0.f;

    for (int kc = 0; kc < 12; kc++) {
        CP_WAIT0();
        __syncthreads();
        uint32_t tcur = s_u + (uint32_t)((kc & 1) * TS_BUF_B);
        if (kc < 11) {
            uint32_t tnext = s_u + (uint32_t)(((kc + 1) & 1) * TS_BUF_B);
            for (int i = tid; i < MTOK * 8; i += 256) {
                int r = i >> 3, s = i & 7;
                cp_async16(tnext + r * TS_ROWB + s * 16,
                           gtokc + r * (CDIM * 2) + (kc + 1) * 128 + s * 16);
            }
            CP_COMMIT();
        }
#pragma unroll
        for (int ks = 0; ks < 4; ks++) {
            uint32_t a[4];
            ldsm_x4(a[0], a[1], a[2], a[3], aA_base + kc * 128 + ks * 32);
#pragma unroll
            for (int tp = 0; tp < 6; tp++) {
                uint32_t b[4];
                ldsm_x4(b[0], b[1], b[2], b[3],
                        tcur + tp * 16 * TS_ROWB + ks * 32 + bL_off144);
                mma16816(acc1[2 * tp], a, b);
                mma16816(acc1[2 * tp + 1], a, b + 2);
            }
            {   // t = 12 (rows 96..103) via x2
                uint32_t b0, b1v;
                uint32_t addr = tcur + (96 + lr) * TS_ROWB + ks * 32 + ((lane >> 3) & 1) * 16;
                ldsm_x2(b0, b1v, addr);
                uint32_t bb[2] = {b0, b1v};
                mma16816(acc1[12], a, bb);
            }
        }
    }

    // ---- Phase 1.5: softmax in registers ----
    const float rsc = 0.03608439182435161f; // 768^-0.5
    float mx0 = -1e30f, mx1 = -1e30f;
#pragma unroll
    for (int t = 0; t < 13; t++)
#pragma unroll
        for (int j = 0; j < 4; j++) {
            int m = t * 8 + tg * 2 + (j & 1);
            float v = acc1[t][j] * rsc;
            acc1[t][j] = v;
            if (m < MT_REAL) { if (j < 2) mx0 = fmaxf(mx0, v); else mx1 = fmaxf(mx1, v); }
        }
    mx0 = fmaxf(mx0, __shfl_xor_sync(0xffffffffu, mx0, 1));
    mx0 = fmaxf(mx0, __shfl_xor_sync(0xffffffffu, mx0, 2));
    mx1 = fmaxf(mx1, __shfl_xor_sync(0xffffffffu, mx1, 1));
    mx1 = fmaxf(mx1, __shfl_xor_sync(0xffffffffu, mx1, 2));
    float s0 = 0.f, s1 = 0.f;
#pragma unroll
    for (int t = 0; t < 13; t++)
#pragma unroll
        for (int j = 0; j < 4; j++) {
            int m = t * 8 + tg * 2 + (j & 1);
            float e = (m < MT_REAL) ? __expf(acc1[t][j] - ((j < 2) ? mx0 : mx1)) : 0.f;
            acc1[t][j] = e;
            if (j < 2) s0 += e; else s1 += e;
        }
    s0 += __shfl_xor_sync(0xffffffffu, s0, 1);
    s0 += __shfl_xor_sync(0xffffffffu, s0, 2);
    s1 += __shfl_xor_sync(0xffffffffu, s1, 1);
    s1 += __shfl_xor_sync(0xffffffffu, s1, 2);
    float inv0 = 1.f / s0, inv1 = 1.f / s1;
    if (tg == 0) { acc1[0][0] = 0.f; acc1[0][2] = 0.f; }  // drop token m=0

    // pack probabilities directly into GEMM2 A-fragments (K = m, 7 chunks of 16)
    uint32_t pa[7][4];
#pragma unroll
    for (int q = 0; q < 7; q++) {
        int t0 = 2 * q;
        pa[q][0] = pack_bf2(acc1[t0][0] * inv0, acc1[t0][1] * inv0);
        pa[q][1] = pack_bf2(acc1[t0][2] * inv1, acc1[t0][3] * inv1);
        if (t0 + 1 < 13) {
            pa[q][2] = pack_bf2(acc1[t0 + 1][0] * inv0, acc1[t0 + 1][1] * inv0);
            pa[q][3] = pack_bf2(acc1[t0 + 1][2] * inv1, acc1[t0 + 1][3] * inv1);
        } else { pa[q][2] = 0u; pa[q][3] = 0u; }
    }

    // ---- Phase 2: delta1 = P @ t1full, y = x + delta1 (in place over Xs) ----
    const char* gt1c = (const char*)g_t1T;
    for (int nc = 0; nc < 12; nc++) {
        __syncthreads();
        for (int i = tid; i < 64 * 15; i += 256) {
            int r = i / 15, s = i % 15;
            cp_async16(s_u + r * S2_ROWB + s * 16,
                       gt1c + (size_t)(nc * 64 + r) * S2_ROWB + s * 16);
        }
        CP_COMMIT();
        CP_WAIT0();
        __syncthreads();
        float acc2[8][4];
#pragma unroll
        for (int t = 0; t < 8; t++)
#pragma unroll
            for (int j = 0; j < 4; j++) acc2[t][j] = 0.f;
#pragma unroll
        for (int q = 0; q < 7; q++) {
#pragma unroll
            for (int tp = 0; tp < 4; tp++) {
                uint32_t b[4];
                ldsm_x4(b[0], b[1], b[2], b[3],
                        s_u + tp * 16 * S2_ROWB + q * 32 + bL_off240);
                mma16816(acc2[2 * tp], pa[q], b);
                mma16816(acc2[2 * tp + 1], pa[q], b + 2);
            }
        }
#pragma unroll
        for (int t = 0; t < 8; t++) {
            int c0 = nc * 64 + t * 8 + tg * 2;
            uint32_t* p0 = &Xu[(wr0 + g) * (XS_STRIDE / 2) + c0 / 2];
            uint32_t* p1 = &Xu[(wr0 + g + 8) * (XS_STRIDE / 2) + c0 / 2];
            __nv_bfloat162 x0 = *(__nv_bfloat162*)p0;
            __nv_bfloat162 x1 = *(__nv_bfloat162*)p1;
            *p0 = pack_bf2(__bfloat162float(x0.x) + acc2[t][0],
                           __bfloat162float(x0.y) + acc2[t][1]);
            *p1 = pack_bf2(__bfloat162float(x1.x) + acc2[t][2],
                           __bfloat162float(x1.y) + acc2[t][3]);
        }
    }

    // ---- Phase 3: out = x + scale * (Y @ w2^T + b2), flattened 144-step pipeline ----
    const float scale = __ldg(scale_p);
    const float2* b2v = (const float2*)b2p;
    const float2* xg2 = (const float2*)xg;
    float2* outg2 = (float2*)(out + 64 * CDIM + (size_t)row0 * CDIM);
    const char* w2c = (const char*)g_w2bf;

    __syncthreads();   // all warps done reading phase-2 stage before B0 overwrite
    // prologue: s = 0 (nc=0, kc=0) into buffer 0
    for (int i = tid; i < 64 * 8; i += 256) {
        int r = i >> 3, s = i & 7;
        cp_async16(s_u + r * B3_ROWB + s * 16, w2c + (size_t)r * (CDIM * 2) + s * 16);
    }
    CP_COMMIT();

    float acc3[8][4];
    for (int st = 0; st < 144; st++) {
        int nc = st / 12, kc = st % 12;
        if (kc == 0) {
#pragma unroll
            for (int t = 0; t < 8; t++)
#pragma unroll
                for (int j = 0; j < 4; j++) acc3[t][j] = 0.f;
        }
        CP_WAIT0();
        __syncthreads();
        uint32_t bcur = s_u + (uint32_t)((st & 1) * B3_BUF_B);
        if (st + 1 < 144) {
            int nn = (st + 1) / 12, nk = (st + 1) % 12;
            uint32_t bnext = s_u + (uint32_t)(((st + 1) & 1) * B3_BUF_B);
            for (int i = tid; i < 64 * 8; i += 256) {
                int r = i >> 3, s = i & 7;
                cp_async16(bnext + r * B3_ROWB + s * 16,
                           w2c + (size_t)(nn * 64 + r) * (CDIM * 2) + nk * 128 + s * 16);
            }
            CP_COMMIT();
        }
#pragma unroll
        for (int ks = 0; ks < 4; ks++) {
            uint32_t a[4];
            ldsm_x4(a[0], a[1], a[2], a[3], aA_base + kc * 128 + ks * 32);
#pragma unroll
            for (int tp = 0; tp < 4; tp++) {
                uint32_t b[4];
                ldsm_x4(b[0], b[1], b[2], b[3],
                        bcur + tp * 16 * B3_ROWB + ks * 32 + bL_off144);
                mma16816(acc3[2 * tp], a, b);
                mma16816(acc3[2 * tp + 1], a, b + 2);
            }
        }
        if (kc == 11) {
            // epilogue: fp32 x re-read + scaled update
#pragma unroll
            for (int t = 0; t < 8; t++) {
                int n = nc * 64 + t * 8 + tg * 2;
                float2 bb = __ldg(&b2v[n >> 1]);
                int r1 = wr0 + g, r2 = r1 + 8;
                float2 x1 = __ldg(&xg2[(size_t)r1 * (CDIM / 2) + (n >> 1)]);
                float2 x2 = __ldg(&xg2[(size_t)r2 * (CDIM / 2) + (n >> 1)]);
                float2 o1, o2;
                o1.x = x1.x + scale * (acc3[t][0] + bb.x);
                o1.y = x1.y + scale * (acc3[t][1] + bb.y);
                o2.x = x2.x + scale * (acc3[t][2] + bb.x);
                o2.y = x2.y + scale * (acc3[t][3] + bb.y);
                outg2[(size_t)r1 * (CDIM / 2) + (n >> 1)] = o1;
                outg2[(size_t)r2 * (CDIM / 2) + (n >> 1)] = o2;
            }
        }
    }
}

// ---------------- launch ----------------

extern "C" void kernel_launch(void* const* d_in, const int* in_sizes, int n_in,
                              void* d_out, int out_size) {
    (void)in_sizes; (void)n_in; (void)out_size;
    const float* feats = (const float*)d_in[0];
    const float* ta    = (const float*)d_in[1];
    const float* tb    = (const float*)d_in[2];
    const float* scale = (const float*)d_in[3];
    const float* w1    = (const float*)d_in[4];
    const float* b1    = (const float*)d_in[5];
    const float* w2    = (const float*)d_in[6];
    const float* b2    = (const float*)d_in[7];
    const int*   layer = (const int*)d_in[8];
    float* out = (float*)d_out;

    prep_tokens<<<(MTOK * CDIM + 255) / 256, 256>>>(ta, tb, layer);
    prep_t1<<<CDIM / T1_CBLK, 128>>>(w1, b1);
    prep_w2<<<(CDIM * CDIM + 255) / 256, 256>>>(w2);
    copy_cls<<<(64 * CDIM / 4 + 255) / 256, 256>>>(feats, out);

    static bool attr_set = false;
    if (!attr_set) {
        cudaFuncSetAttribute(lst_main, cudaFuncAttributeMaxDynamicSharedMemorySize, SMEM_BYTES);
        attr_set = true;
    }
    lst_main<<<65536 / MTILE, 256, SMEM_BYTES>>>(feats, b2, scale, out);
}

// round 5
// speedup vs baseline: 1.4653x; 1.1521x over previous
#include <cuda_runtime.h>
#include <cuda_bf16.h>
#include <cstdint>

#define CDIM 768
#define MTOK 104
#define MT_REAL 100
#define MTILE 128
#define XS_STRIDE 776          // bf16 per Xs row (768+8 pad)
#define XS_ROWB 1552
#define XS_SZ (MTILE*XS_ROWB)  // 198656
#define STAGE_B 16384          // per stage buffer
#define MB_OFF (XS_SZ + 2*STAGE_B)   // 231424
#define SMEM_BYTES (MB_OFF + 64)     // 231488
#define TOK_CH_B (MTOK*128)    // 13312
#define T1_CH_B  (64*256)      // 16384
#define W2_CH_B  (64*128)      // 8192

__device__ __align__(16) float g_tokens[MT_REAL * CDIM];
__device__ __align__(16) __nv_bfloat16 g_tok_t[12 * MTOK * 64];   // tiled+swizzled
__device__ __align__(16) __nv_bfloat16 g_t1t[12 * 64 * 128];      // tiled+swizzled
__device__ __align__(16) __nv_bfloat16 g_w2t[144 * 64 * 64];      // tiled+swizzled

__device__ __forceinline__ uint32_t pack_bf2(float a, float b) {
    __nv_bfloat162 h = __floats2bfloat162_rn(a, b);
    return *reinterpret_cast<uint32_t*>(&h);
}

__device__ __forceinline__ void mma16816(float* d, const uint32_t* a, const uint32_t* b) {
    asm volatile(
        "mma.sync.aligned.m16n8k16.row.col.f32.bf16.bf16.f32 "
        "{%0,%1,%2,%3}, {%4,%5,%6,%7}, {%8,%9}, {%0,%1,%2,%3};"
        : "+f"(d[0]), "+f"(d[1]), "+f"(d[2]), "+f"(d[3])
        : "r"(a[0]), "r"(a[1]), "r"(a[2]), "r"(a[3]), "r"(b[0]), "r"(b[1]));
}

__device__ __forceinline__ void ldsm_x4(uint32_t& r0, uint32_t& r1, uint32_t& r2, uint32_t& r3,
                                        uint32_t addr) {
    asm volatile("ldmatrix.sync.aligned.m8n8.x4.shared.b16 {%0,%1,%2,%3}, [%4];"
                 : "=r"(r0), "=r"(r1), "=r"(r2), "=r"(r3) : "r"(addr));
}
__device__ __forceinline__ void ldsm_x2(uint32_t& r0, uint32_t& r1, uint32_t addr) {
    asm volatile("ldmatrix.sync.aligned.m8n8.x2.shared.b16 {%0,%1}, [%2];"
                 : "=r"(r0), "=r"(r1) : "r"(addr));
}

__device__ __forceinline__ void mbar_init(uint32_t mbar) {
    asm volatile("mbarrier.init.shared.b64 [%0], %1;" :: "r"(mbar), "r"(1) : "memory");
}
__device__ __forceinline__ void bulk_load(uint32_t dst, const void* src, uint32_t bytes,
                                          uint32_t mbar) {
    asm volatile("mbarrier.arrive.expect_tx.shared.b64 _, [%0], %1;"
                 :: "r"(mbar), "r"(bytes) : "memory");
    asm volatile("cp.async.bulk.shared::cta.global.mbarrier::complete_tx::bytes "
                 "[%0], [%1], %2, [%3];"
                 :: "r"(dst), "l"(src), "r"(bytes), "r"(mbar) : "memory");
}
__device__ __forceinline__ void mbar_wait(uint32_t mbar, uint32_t parity) {
    asm volatile(
        "{\n\t"
        ".reg .pred P1;\n\t"
        "LAB_WAIT_%=:\n\t"
        "mbarrier.try_wait.parity.acquire.cta.shared::cta.b64 P1, [%0], %1, 0x989680;\n\t"
        "@P1 bra LAB_DONE_%=;\n\t"
        "bra LAB_WAIT_%=;\n\t"
        "LAB_DONE_%=:\n\t"
        "}" :: "r"(mbar), "r"(parity) : "memory");
}

// ---------------- prep kernels ----------------

__global__ void prep_tokens(const float* __restrict__ ta, const float* __restrict__ tb,
                            const int* __restrict__ layer_p) {
    int L = __ldg(layer_p);
    int i = blockIdx.x * 256 + threadIdx.x;
    if (i >= MTOK * CDIM) return;
    int m = i / CDIM, c = i % CDIM;
    float acc = 0.f;
    if (m < MT_REAL) {
        const float* a = ta + (size_t)L * MT_REAL * 32 + m * 32;
        const float* b = tb + (size_t)L * 32 * CDIM + c;
#pragma unroll
        for (int k = 0; k < 32; k++) acc += __ldg(a + k) * __ldg(b + k * CDIM);
        g_tokens[m * CDIM + c] = acc;
    }
    int kc = c >> 6, s = (c >> 3) & 7, e = c & 7;
    g_tok_t[((kc * MTOK + m) << 6) + ((s ^ (m & 7)) << 3) + e] = __float2bfloat16(acc);
}

#define T1_CBLK 8
__global__ void prep_t1(const float* __restrict__ w1, const float* __restrict__ b1) {
    __shared__ float w1s[T1_CBLK][CDIM];
    int c0 = blockIdx.x * T1_CBLK;
    for (int i = threadIdx.x; i < T1_CBLK * CDIM; i += blockDim.x)
        w1s[i / CDIM][i % CDIM] = __ldg(&w1[(size_t)(c0 + i / CDIM) * CDIM + (i % CDIM)]);
    __syncthreads();
    int m = threadIdx.x;   // 0..127
    float acc[T1_CBLK];
#pragma unroll
    for (int j = 0; j < T1_CBLK; j++) acc[j] = 0.f;
    bool live = (m >= 1 && m < MT_REAL);
    if (live) {
        const float* tok = g_tokens + (size_t)m * CDIM;
#pragma unroll 4
        for (int k = 0; k < CDIM; k++) {
            float tv = tok[k];
#pragma unroll
            for (int j = 0; j < T1_CBLK; j++) acc[j] += tv * w1s[j][k];
        }
    }
#pragma unroll
    for (int j = 0; j < T1_CBLK; j++) {
        float v = live ? (acc[j] + __ldg(b1 + c0 + j)) : 0.f;
        int c = c0 + j, nc = c >> 6, rr = c & 63;
        int off = ((nc * 64 + rr) << 7) + ((m >> 6) << 6) + ((((m >> 3) & 7) ^ (rr & 7)) << 3) + (m & 7);
        g_t1t[off] = __float2bfloat16(v);
    }
}

__global__ void prep_w2(const float* __restrict__ w2) {
    // one thread per 8-element unit: 73728 units
    int i = blockIdx.x * 256 + threadIdx.x;
    if (i >= CDIM * CDIM / 8) return;
    int r = i / 96, cu = i % 96, c0 = cu * 8;
    const float4* v = (const float4*)(w2 + (size_t)r * CDIM + c0);
    float4 v0 = __ldg(v), v1 = __ldg(v + 1);
    uint32_t u[4];
    u[0] = pack_bf2(v0.x, v0.y); u[1] = pack_bf2(v0.z, v0.w);
    u[2] = pack_bf2(v1.x, v1.y); u[3] = pack_bf2(v1.z, v1.w);
    int nc = r >> 6, rr = r & 63, kcb = c0 >> 6, s = (c0 >> 3) & 7;
    int off = (((nc * 12 + kcb) * 64 + rr) << 6) + ((s ^ (rr & 7)) << 3);
    *(uint4*)(g_w2t + off) = *(uint4*)u;
}

__global__ void copy_cls(const float* __restrict__ feats, float* __restrict__ out) {
    int i = blockIdx.x * 256 + threadIdx.x;
    if (i < 64 * CDIM / 4) ((float4*)out)[i] = ((const float4*)feats)[i];
}

// ---------------- fused main kernel ----------------

__global__ __launch_bounds__(256, 1) void lst_main(
    const float* __restrict__ feats, const float* __restrict__ b2p,
    const float* __restrict__ scale_p, float* __restrict__ out) {
    extern __shared__ __align__(16) char smem_raw[];
    uint32_t* Xu = (uint32_t*)smem_raw;

    const uint32_t xs_u = (uint32_t)__cvta_generic_to_shared(smem_raw);
    const uint32_t s_u = xs_u + XS_SZ;
    const uint32_t mb_u = xs_u + MB_OFF;

    const int tid = threadIdx.x;
    const int w = tid >> 5, lane = tid & 31;
    const int g = lane >> 2, tg = lane & 3;
    const int wr0 = w * 16;
    const int p = lane >> 3, lr = lane & 7;
    const int row0 = blockIdx.x * MTILE;
    const float* xg = feats + 64 * CDIM + (size_t)row0 * CDIM;

    // ldmatrix lane bases
    const uint32_t aA_base = xs_u + (wr0 + ((p & 1) << 3) + lr) * XS_ROWB + ((p >> 1) << 4);
    const int bRow = ((p >> 1) << 3) + lr;        // 0..15
    const int bCol16 = p & 1;                     // 16B col select

    // ---- mbarrier init ----
    if (tid == 0) {
#pragma unroll
        for (int i = 0; i < 6; i++) mbar_init(mb_u + i * 8);
    }
    __syncthreads();
    // prologue: tokens chunk 0 -> buf0
    if (tid == 0) bulk_load(s_u, g_tok_t, TOK_CH_B, mb_u + 0);

    // ---- Phase 0: x tile -> bf16 smem ----
    for (int i = tid; i < MTILE * (CDIM / 4); i += 256) {
        int r = i / (CDIM / 4);
        int c4 = i % (CDIM / 4);
        float4 v = __ldg(&((const float4*)xg)[(size_t)r * (CDIM / 4) + c4]);
        Xu[r * (XS_STRIDE / 2) + c4 * 2] = pack_bf2(v.x, v.y);
        Xu[r * (XS_STRIDE / 2) + c4 * 2 + 1] = pack_bf2(v.z, v.w);
    }

    // ---- Phase 1: GEMM1 logits = X @ tokens^T ----
    float acc1[13][4];
#pragma unroll
    for (int t = 0; t < 13; t++)
#pragma unroll
        for (int j = 0; j < 4; j++) acc1[t][j] = 0.f;

    for (int kc = 0; kc < 12; kc++) {
        __syncthreads();   // prior readers of other buffer done (also orders Phase 0 at kc=0)
        if (tid == 0 && kc < 11)
            bulk_load(s_u + ((kc + 1) & 1) * STAGE_B, (const char*)g_tok_t + (kc + 1) * TOK_CH_B,
                      TOK_CH_B, mb_u + ((kc + 1) & 1) * 8);
        mbar_wait(mb_u + (kc & 1) * 8, (kc >> 1) & 1);
        uint32_t tcur = s_u + (kc & 1) * STAGE_B;
#pragma unroll
        for (int ks = 0; ks < 4; ks++) {
            uint32_t a[4];
            ldsm_x4(a[0], a[1], a[2], a[3], aA_base + kc * 128 + ks * 32);
#pragma unroll
            for (int tp = 0; tp < 6; tp++) {
                uint32_t b[4];
                ldsm_x4(b[0], b[1], b[2], b[3],
                        tcur + (tp * 16 + bRow) * 128 + (((ks << 1) + bCol16) ^ lr) * 16);
                mma16816(acc1[2 * tp], a, b);
                mma16816(acc1[2 * tp + 1], a, b + 2);
            }
            {   // rows 96..103 via x2
                uint32_t b0, b1v;
                uint32_t addr = tcur + (96 + lr) * 128 + (((ks << 1) + ((lane >> 3) & 1)) ^ lr) * 16;
                ldsm_x2(b0, b1v, addr);
                uint32_t bb[2] = {b0, b1v};
                mma16816(acc1[12], a, bb);
            }
        }
    }

    // ---- Phase 1.5: softmax in registers ----
    const float rsc = 0.03608439182435161f; // 768^-0.5
    float mx0 = -1e30f, mx1 = -1e30f;
#pragma unroll
    for (int t = 0; t < 13; t++)
#pragma unroll
        for (int j = 0; j < 4; j++) {
            int m = t * 8 + tg * 2 + (j & 1);
            float v = acc1[t][j] * rsc;
            acc1[t][j] = v;
            if (m < MT_REAL) { if (j < 2) mx0 = fmaxf(mx0, v); else mx1 = fmaxf(mx1, v); }
        }
    mx0 = fmaxf(mx0, __shfl_xor_sync(0xffffffffu, mx0, 1));
    mx0 = fmaxf(mx0, __shfl_xor_sync(0xffffffffu, mx0, 2));
    mx1 = fmaxf(mx1, __shfl_xor_sync(0xffffffffu, mx1, 1));
    mx1 = fmaxf(mx1, __shfl_xor_sync(0xffffffffu, mx1, 2));
    float s0 = 0.f, s1 = 0.f;
#pragma unroll
    for (int t = 0; t < 13; t++)
#pragma unroll
        for (int j = 0; j < 4; j++) {
            int m = t * 8 + tg * 2 + (j & 1);
            float e = (m < MT_REAL) ? __expf(acc1[t][j] - ((j < 2) ? mx0 : mx1)) : 0.f;
            acc1[t][j] = e;
            if (j < 2) s0 += e; else s1 += e;
        }
    s0 += __shfl_xor_sync(0xffffffffu, s0, 1);
    s0 += __shfl_xor_sync(0xffffffffu, s0, 2);
    s1 += __shfl_xor_sync(0xffffffffu, s1, 1);
    s1 += __shfl_xor_sync(0xffffffffu, s1, 2);
    float inv0 = 1.f / s0, inv1 = 1.f / s1;
    if (tg == 0) { acc1[0][0] = 0.f; acc1[0][2] = 0.f; }  // drop token m=0

    uint32_t pa[7][4];
#pragma unroll
    for (int q = 0; q < 7; q++) {
        int t0 = 2 * q;
        pa[q][0] = pack_bf2(acc1[t0][0] * inv0, acc1[t0][1] * inv0);
        pa[q][1] = pack_bf2(acc1[t0][2] * inv1, acc1[t0][3] * inv1);
        if (t0 + 1 < 13) {
            pa[q][2] = pack_bf2(acc1[t0 + 1][0] * inv0, acc1[t0 + 1][1] * inv0);
            pa[q][3] = pack_bf2(acc1[t0 + 1][2] * inv1, acc1[t0 + 1][3] * inv1);
        } else { pa[q][2] = 0u; pa[q][3] = 0u; }
    }

    // ---- Phase 2: delta1 = P @ t1full, y = x + delta1 (in place over Xs) ----
    if (tid == 0) bulk_load(s_u, g_t1t, T1_CH_B, mb_u + 16);   // buf0 free (phase1 kc=10 readers synced)
    for (int nc = 0; nc < 12; nc++) {
        __syncthreads();
        if (tid == 0 && nc < 11)
            bulk_load(s_u + ((nc + 1) & 1) * STAGE_B, (const char*)g_t1t + (nc + 1) * T1_CH_B,
                      T1_CH_B, mb_u + 16 + ((nc + 1) & 1) * 8);
        mbar_wait(mb_u + 16 + (nc & 1) * 8, (nc >> 1) & 1);
        uint32_t scur = s_u + (nc & 1) * STAGE_B;
        float acc2[8][4];
#pragma unroll
        for (int t = 0; t < 8; t++)
#pragma unroll
            for (int j = 0; j < 4; j++) acc2[t][j] = 0.f;
#pragma unroll
        for (int q = 0; q < 7; q++) {
            int u2 = 2 * q + bCol16;
#pragma unroll
            for (int tp = 0; tp < 4; tp++) {
                uint32_t b[4];
                ldsm_x4(b[0], b[1], b[2], b[3],
                        scur + (tp * 16 + bRow) * 256 + (u2 >> 3) * 128 + ((u2 & 7) ^ lr) * 16);
                mma16816(acc2[2 * tp], pa[q], b);
                mma16816(acc2[2 * tp + 1], pa[q], b + 2);
            }
        }
#pragma unroll
        for (int t = 0; t < 8; t++) {
            int c0 = nc * 64 + t * 8 + tg * 2;
            uint32_t* p0 = &Xu[(wr0 + g) * (XS_STRIDE / 2) + c0 / 2];
            uint32_t* p1 = &Xu[(wr0 + g + 8) * (XS_STRIDE / 2) + c0 / 2];
            __nv_bfloat162 x0 = *(__nv_bfloat162*)p0;
            __nv_bfloat162 x1 = *(__nv_bfloat162*)p1;
            *p0 = pack_bf2(__bfloat162float(x0.x) + acc2[t][0],
                           __bfloat162float(x0.y) + acc2[t][1]);
            *p1 = pack_bf2(__bfloat162float(x1.x) + acc2[t][2],
                           __bfloat162float(x1.y) + acc2[t][3]);
        }
    }

    // ---- Phase 3: out = x + scale * (Y @ w2^T + b2), 144-step bulk pipeline ----
    const float scale = __ldg(scale_p);
    const float2* b2v = (const float2*)b2p;
    const float2* xg2 = (const float2*)xg;
    float2* outg2 = (float2*)(out + 64 * CDIM + (size_t)row0 * CDIM);

    if (tid == 0) bulk_load(s_u, g_w2t, W2_CH_B, mb_u + 32);   // buf0 free (phase2 nc=10 synced)
    float acc3[8][4];
    for (int st = 0; st < 144; st++) {
        int nc = st / 12, kc = st % 12;
        if (kc == 0) {
#pragma unroll
            for (int t = 0; t < 8; t++)
#pragma unroll
                for (int j = 0; j < 4; j++) acc3[t][j] = 0.f;
        }
        __syncthreads();
        if (tid == 0 && st < 143)
            bulk_load(s_u + ((st + 1) & 1) * STAGE_B, (const char*)g_w2t + (st + 1) * W2_CH_B,
                      W2_CH_B, mb_u + 32 + ((st + 1) & 1) * 8);
        mbar_wait(mb_u + 32 + (st & 1) * 8, (st >> 1) & 1);
        uint32_t bcur = s_u + (st & 1) * STAGE_B;
#pragma unroll
        for (int ks = 0; ks < 4; ks++) {
            uint32_t a[4];
            ldsm_x4(a[0], a[1], a[2], a[3], aA_base + kc * 128 + ks * 32);
#pragma unroll
            for (int tp = 0; tp < 4; tp++) {
                uint32_t b[4];
                ldsm_x4(b[0], b[1], b[2], b[3],
                        bcur + (tp * 16 + bRow) * 128 + (((ks << 1) + bCol16) ^ lr) * 16);
                mma16816(acc3[2 * tp], a, b);
                mma16816(acc3[2 * tp + 1], a, b + 2);
            }
        }
        if (kc == 11) {
#pragma unroll
            for (int t = 0; t < 8; t++) {
                int n = nc * 64 + t * 8 + tg * 2;
                float2 bb = __ldg(&b2v[n >> 1]);
                int r1 = wr0 + g, r2 = r1 + 8;
                float2 x1 = __ldg(&xg2[(size_t)r1 * (CDIM / 2) + (n >> 1)]);
                float2 x2 = __ldg(&xg2[(size_t)r2 * (CDIM / 2) + (n >> 1)]);
                float2 o1, o2;
                o1.x = x1.x + scale * (acc3[t][0] + bb.x);
                o1.y = x1.y + scale * (acc3[t][1] + bb.y);
                o2.x = x2.x + scale * (acc3[t][2] + bb.x);
                o2.y = x2.y + scale * (acc3[t][3] + bb.y);
                outg2[(size_t)r1 * (CDIM / 2) + (n >> 1)] = o1;
                outg2[(size_t)r2 * (CDIM / 2) + (n >> 1)] = o2;
            }
        }
    }
}

// ---------------- launch ----------------

extern "C" void kernel_launch(void* const* d_in, const int* in_sizes, int n_in,
                              void* d_out, int out_size) {
    (void)in_sizes; (void)n_in; (void)out_size;
    const float* feats = (const float*)d_in[0];
    const float* ta    = (const float*)d_in[1];
    const float* tb    = (const float*)d_in[2];
    const float* scale = (const float*)d_in[3];
    const float* w1    = (const float*)d_in[4];
    const float* b1    = (const float*)d_in[5];
    const float* w2    = (const float*)d_in[6];
    const float* b2    = (const float*)d_in[7];
    const int*   layer = (const int*)d_in[8];
    float* out = (float*)d_out;

    prep_tokens<<<(MTOK * CDIM + 255) / 256, 256>>>(ta, tb, layer);
    prep_t1<<<CDIM / T1_CBLK, 128>>>(w1, b1);
    prep_w2<<<(CDIM * CDIM / 8 + 255) / 256, 256>>>(w2);
    copy_cls<<<(64 * CDIM / 4 + 255) / 256, 256>>>(feats, out);

    static bool attr_set = false;
    if (!attr_set) {
        cudaFuncSetAttribute(lst_main, cudaFuncAttributeMaxDynamicSharedMemorySize, SMEM_BYTES);
        attr_set = true;
    }
    lst_main<<<65536 / MTILE, 256, SMEM_BYTES>>>(feats, b2, scale, out);
}

// round 13
// speedup vs baseline: 1.5377x; 1.0494x over previous
#include <cuda_runtime.h>
#include <cuda_bf16.h>
#include <cstdint>

#define CDIM 768
#define MTOK 104
#define MT_REAL 100
#define MTILE 128
#define XS_STRIDE 776          // bf16 per Xs row (768+8 pad)
#define XS_ROWB 1552
#define XS_SZ (MTILE*XS_ROWB)  // 198656
#define STAGE_B 16384
#define MB_OFF (XS_SZ + 2*STAGE_B)   // 231424
#define SMEM_BYTES (MB_OFF + 64)     // 231488
#define TOK_CH_B (MTOK*128)    // 13312
#define T1_CH_B  (64*256)      // 16384
#define W2_CH_B  8192          // one 64x64 k-block per step

__device__ __align__(16) float g_tokens[MT_REAL * CDIM];
__device__ __align__(16) __nv_bfloat16 g_tok_t[12 * MTOK * 64];   // swizzled k-blocks
__device__ __align__(16) __nv_bfloat16 g_t1t[12 * 64 * 128];      // swizzled
__device__ __align__(16) __nv_bfloat16 g_w2t[144 * 64 * 64];      // swizzled 8KB blocks

__device__ __forceinline__ uint32_t pack_bf2(float a, float b) {
    __nv_bfloat162 h = __floats2bfloat162_rn(a, b);
    return *reinterpret_cast<uint32_t*>(&h);
}
__device__ __forceinline__ void mma16816(float* d, const uint32_t* a, const uint32_t* b) {
    asm volatile(
        "mma.sync.aligned.m16n8k16.row.col.f32.bf16.bf16.f32 "
        "{%0,%1,%2,%3}, {%4,%5,%6,%7}, {%8,%9}, {%0,%1,%2,%3};"
        : "+f"(d[0]), "+f"(d[1]), "+f"(d[2]), "+f"(d[3])
        : "r"(a[0]), "r"(a[1]), "r"(a[2]), "r"(a[3]), "r"(b[0]), "r"(b[1]));
}
__device__ __forceinline__ void ldsm_x4(uint32_t& r0, uint32_t& r1, uint32_t& r2, uint32_t& r3,
                                        uint32_t addr) {
    asm volatile("ldmatrix.sync.aligned.m8n8.x4.shared.b16 {%0,%1,%2,%3}, [%4];"
                 : "=r"(r0), "=r"(r1), "=r"(r2), "=r"(r3) : "r"(addr));
}
__device__ __forceinline__ void ldsm_x2(uint32_t& r0, uint32_t& r1, uint32_t addr) {
    asm volatile("ldmatrix.sync.aligned.m8n8.x2.shared.b16 {%0,%1}, [%2];"
                 : "=r"(r0), "=r"(r1) : "r"(addr));
}
__device__ __forceinline__ void mbar_init(uint32_t mbar, uint32_t cnt) {
    asm volatile("mbarrier.init.shared.b64 [%0], %1;" :: "r"(mbar), "r"(cnt) : "memory");
}
__device__ __forceinline__ void bulk_load(uint32_t dst, const void* src, uint32_t bytes,
                                          uint32_t mbar) {
    asm volatile("mbarrier.arrive.expect_tx.shared.b64 _, [%0], %1;"
                 :: "r"(mbar), "r"(bytes) : "memory");
    asm volatile("cp.async.bulk.shared::cta.global.mbarrier::complete_tx::bytes "
                 "[%0], [%1], %2, [%3];"
                 :: "r"(dst), "l"(src), "r"(bytes), "r"(mbar) : "memory");
}
__device__ __forceinline__ void mbar_wait(uint32_t mbar, uint32_t parity) {
    asm volatile(
        "{\n\t"
        ".reg .pred P1;\n\t"
        "LAB_WAIT_%=:\n\t"
        "mbarrier.try_wait.parity.acquire.cta.shared::cta.b64 P1, [%0], %1, 0x989680;\n\t"
        "@P1 bra LAB_DONE_%=;\n\t"
        "bra LAB_WAIT_%=;\n\t"
        "LAB_DONE_%=:\n\t"
        "}" :: "r"(mbar), "r"(parity) : "memory");
}

// ---------------- prep kernels ----------------

__global__ void prep_tokens(const float* __restrict__ ta, const float* __restrict__ tb,
                            const int* __restrict__ layer_p) {
    int L = __ldg(layer_p);
    int i = blockIdx.x * 256 + threadIdx.x;
    if (i >= MTOK * CDIM) return;
    int m = i / CDIM, c = i % CDIM;
    float acc = 0.f;
    if (m < MT_REAL) {
        const float* a = ta + (size_t)L * MT_REAL * 32 + m * 32;
        const float* b = tb + (size_t)L * 32 * CDIM + c;
#pragma unroll
        for (int k = 0; k < 32; k++) acc += __ldg(a + k) * __ldg(b + k * CDIM);
        g_tokens[m * CDIM + c] = acc;
    }
    int kc = c >> 6, s = (c >> 3) & 7, e = c & 7;
    g_tok_t[((kc * MTOK + m) << 6) + ((s ^ (m & 7)) << 3) + e] = __float2bfloat16(acc);
}

#define T1_CBLK 8
__global__ void prep_t1(const float* __restrict__ w1, const float* __restrict__ b1) {
    __shared__ float w1s[T1_CBLK][CDIM];
    int c0 = blockIdx.x * T1_CBLK;
    for (int i = threadIdx.x; i < T1_CBLK * CDIM; i += blockDim.x)
        w1s[i / CDIM][i % CDIM] = __ldg(&w1[(size_t)(c0 + i / CDIM) * CDIM + (i % CDIM)]);
    __syncthreads();
    int m = threadIdx.x;
    float acc[T1_CBLK];
#pragma unroll
    for (int j = 0; j < T1_CBLK; j++) acc[j] = 0.f;
    bool live = (m >= 1 && m < MT_REAL);
    if (live) {
        const float* tok = g_tokens + (size_t)m * CDIM;
#pragma unroll 4
        for (int k = 0; k < CDIM; k++) {
            float tv = tok[k];
#pragma unroll
            for (int j = 0; j < T1_CBLK; j++) acc[j] += tv * w1s[j][k];
        }
    }
#pragma unroll
    for (int j = 0; j < T1_CBLK; j++) {
        float v = live ? (acc[j] + __ldg(b1 + c0 + j)) : 0.f;
        int c = c0 + j, nc = c >> 6, rr = c & 63;
        int off = ((nc * 64 + rr) << 7) + ((m >> 6) << 6) + ((((m >> 3) & 7) ^ (rr & 7)) << 3) + (m & 7);
        g_t1t[off] = __float2bfloat16(v);
    }
}

__global__ void prep_w2(const float* __restrict__ w2) {
    int i = blockIdx.x * 256 + threadIdx.x;
    if (i >= CDIM * CDIM / 8) return;
    int r = i / 96, cu = i % 96, c0 = cu * 8;
    const float4* v = (const float4*)(w2 + (size_t)r * CDIM + c0);
    float4 v0 = __ldg(v), v1 = __ldg(v + 1);
    uint32_t u[4];
    u[0] = pack_bf2(v0.x, v0.y); u[1] = pack_bf2(v0.z, v0.w);
    u[2] = pack_bf2(v1.x, v1.y); u[3] = pack_bf2(v1.z, v1.w);
    int nc = r >> 6, rr = r & 63, kcb = c0 >> 6, s = (c0 >> 3) & 7;
    int off = (((nc * 12 + kcb) * 64 + rr) << 6) + ((s ^ (rr & 7)) << 3);
    *(uint4*)(g_w2t + off) = *(uint4*)u;
}

__global__ void copy_cls(const float* __restrict__ feats, float* __restrict__ out) {
    int i = blockIdx.x * 256 + threadIdx.x;
    if (i < 64 * CDIM / 4) ((float4*)out)[i] = ((const float4*)feats)[i];
}

// ---------------- fused main kernel ----------------

__global__ __launch_bounds__(256, 1) void lst_main(
    const float* __restrict__ feats, const float* __restrict__ b2p,
    const float* __restrict__ scale_p, float* __restrict__ out) {
    extern __shared__ __align__(16) char smem_raw[];
    uint32_t* Xu = (uint32_t*)smem_raw;

    const uint32_t xs_u = (uint32_t)__cvta_generic_to_shared(smem_raw);
    const uint32_t s_u = xs_u + XS_SZ;
    const uint32_t mb_u = xs_u + MB_OFF;

    const int tid = threadIdx.x;
    const int w = tid >> 5, lane = tid & 31;
    const int g = lane >> 2, tg = lane & 3;
    const int wr0 = w * 16;
    const int p = lane >> 3, lr = lane & 7;
    const int row0 = blockIdx.x * MTILE;
    const float* xg = feats + 64 * CDIM + (size_t)row0 * CDIM;

    const uint32_t aA_base = xs_u + (wr0 + ((p & 1) << 3) + lr) * XS_ROWB + ((p >> 1) << 4);
    const int bRow = ((p >> 1) << 3) + lr;
    const int bCol16 = p & 1;

    if (tid == 0) {
#pragma unroll
        for (int i = 0; i < 6; i++) mbar_init(mb_u + i * 8, 1);
    }
    __syncthreads();

    // prologue: tokens chunk 0 -> buf0
    if (tid == 0) bulk_load(s_u, g_tok_t, TOK_CH_B, mb_u + 0);

    // ---- Phase 0: x tile -> bf16 smem ----
    for (int i = tid; i < MTILE * (CDIM / 4); i += 256) {
        int r = i / (CDIM / 4);
        int c4 = i % (CDIM / 4);
        float4 v = __ldg(&((const float4*)xg)[(size_t)r * (CDIM / 4) + c4]);
        Xu[r * (XS_STRIDE / 2) + c4 * 2] = pack_bf2(v.x, v.y);
        Xu[r * (XS_STRIDE / 2) + c4 * 2 + 1] = pack_bf2(v.z, v.w);
    }

    // ---- Phase 1: GEMM1 logits = X @ tokens^T ----
    float acc1[13][4];
#pragma unroll
    for (int t = 0; t < 13; t++)
#pragma unroll
        for (int j = 0; j < 4; j++) acc1[t][j] = 0.f;

    for (int kc = 0; kc < 12; kc++) {
        __syncthreads();
        if (tid == 0 && kc < 11)
            bulk_load(s_u + ((kc + 1) & 1) * STAGE_B, (const char*)g_tok_t + (kc + 1) * TOK_CH_B,
                      TOK_CH_B, mb_u + ((kc + 1) & 1) * 8);
        mbar_wait(mb_u + (kc & 1) * 8, (kc >> 1) & 1);
        uint32_t tcur = s_u + (kc & 1) * STAGE_B;
#pragma unroll
        for (int ks = 0; ks < 4; ks++) {
            uint32_t a[4];
            ldsm_x4(a[0], a[1], a[2], a[3], aA_base + kc * 128 + ks * 32);
#pragma unroll
            for (int tp = 0; tp < 6; tp++) {
                uint32_t b[4];
                ldsm_x4(b[0], b[1], b[2], b[3],
                        tcur + (tp * 16 + bRow) * 128 + (((ks << 1) + bCol16) ^ lr) * 16);
                mma16816(acc1[2 * tp], a, b);
                mma16816(acc1[2 * tp + 1], a, b + 2);
            }
            {
                uint32_t b0, b1v;
                uint32_t addr = tcur + (96 + lr) * 128 + (((ks << 1) + ((lane >> 3) & 1)) ^ lr) * 16;
                ldsm_x2(b0, b1v, addr);
                uint32_t bb[2] = {b0, b1v};
                mma16816(acc1[12], a, bb);
            }
        }
    }

    // ---- Phase 1.5: softmax in registers ----
    const float rsc = 0.03608439182435161f;
    float mx0 = -1e30f, mx1 = -1e30f;
#pragma unroll
    for (int t = 0; t < 13; t++)
#pragma unroll
        for (int j = 0; j < 4; j++) {
            int m = t * 8 + tg * 2 + (j & 1);
            float v = acc1[t][j] * rsc;
            acc1[t][j] = v;
            if (m < MT_REAL) { if (j < 2) mx0 = fmaxf(mx0, v); else mx1 = fmaxf(mx1, v); }
        }
    mx0 = fmaxf(mx0, __shfl_xor_sync(0xffffffffu, mx0, 1));
    mx0 = fmaxf(mx0, __shfl_xor_sync(0xffffffffu, mx0, 2));
    mx1 = fmaxf(mx1, __shfl_xor_sync(0xffffffffu, mx1, 1));
    mx1 = fmaxf(mx1, __shfl_xor_sync(0xffffffffu, mx1, 2));
    float s0 = 0.f, s1 = 0.f;
#pragma unroll
    for (int t = 0; t < 13; t++)
#pragma unroll
        for (int j = 0; j < 4; j++) {
            int m = t * 8 + tg * 2 + (j & 1);
            float e = (m < MT_REAL) ? __expf(acc1[t][j] - ((j < 2) ? mx0 : mx1)) : 0.f;
            acc1[t][j] = e;
            if (j < 2) s0 += e; else s1 += e;
        }
    s0 += __shfl_xor_sync(0xffffffffu, s0, 1);
    s0 += __shfl_xor_sync(0xffffffffu, s0, 2);
    s1 += __shfl_xor_sync(0xffffffffu, s1, 1);
    s1 += __shfl_xor_sync(0xffffffffu, s1, 2);
    float inv0 = 1.f / s0, inv1 = 1.f / s1;
    if (tg == 0) { acc1[0][0] = 0.f; acc1[0][2] = 0.f; }

    uint32_t pa[7][4];
#pragma unroll
    for (int q = 0; q < 7; q++) {
        int t0 = 2 * q;
        pa[q][0] = pack_bf2(acc1[t0][0] * inv0, acc1[t0][1] * inv0);
        pa[q][1] = pack_bf2(acc1[t0][2] * inv1, acc1[t0][3] * inv1);
        if (t0 + 1 < 13) {
            pa[q][2] = pack_bf2(acc1[t0 + 1][0] * inv0, acc1[t0 + 1][1] * inv0);
            pa[q][3] = pack_bf2(acc1[t0 + 1][2] * inv1, acc1[t0 + 1][3] * inv1);
        } else { pa[q][2] = 0u; pa[q][3] = 0u; }
    }

    // ---- Phase 2: delta1 = P @ t1full, y = x + delta1 (in place over Xs) ----
    if (tid == 0) bulk_load(s_u, g_t1t, T1_CH_B, mb_u + 16);
    for (int nc = 0; nc < 12; nc++) {
        __syncthreads();
        if (tid == 0 && nc < 11)
            bulk_load(s_u + ((nc + 1) & 1) * STAGE_B, (const char*)g_t1t + (nc + 1) * T1_CH_B,
                      T1_CH_B, mb_u + 16 + ((nc + 1) & 1) * 8);
        mbar_wait(mb_u + 16 + (nc & 1) * 8, (nc >> 1) & 1);
        uint32_t scur = s_u + (nc & 1) * STAGE_B;
        float acc2[8][4];
#pragma unroll
        for (int t = 0; t < 8; t++)
#pragma unroll
            for (int j = 0; j < 4; j++) acc2[t][j] = 0.f;
#pragma unroll
        for (int q = 0; q < 7; q++) {
            int u2 = 2 * q + bCol16;
#pragma unroll
            for (int tp = 0; tp < 4; tp++) {
                uint32_t b[4];
                ldsm_x4(b[0], b[1], b[2], b[3],
                        scur + (tp * 16 + bRow) * 256 + (u2 >> 3) * 128 + ((u2 & 7) ^ lr) * 16);
                mma16816(acc2[2 * tp], pa[q], b);
                mma16816(acc2[2 * tp + 1], pa[q], b + 2);
            }
        }
#pragma unroll
        for (int t = 0; t < 8; t++) {
            int c0 = nc * 64 + t * 8 + tg * 2;
            uint32_t* p0 = &Xu[(wr0 + g) * (XS_STRIDE / 2) + c0 / 2];
            uint32_t* p1 = &Xu[(wr0 + g + 8) * (XS_STRIDE / 2) + c0 / 2];
            __nv_bfloat162 x0 = *(__nv_bfloat162*)p0;
            __nv_bfloat162 x1 = *(__nv_bfloat162*)p1;
            *p0 = pack_bf2(__bfloat162float(x0.x) + acc2[t][0],
                           __bfloat162float(x0.y) + acc2[t][1]);
            *p1 = pack_bf2(__bfloat162float(x1.x) + acc2[t][2],
                           __bfloat162float(x1.y) + acc2[t][3]);
        }
    }

    // ---- Phase 3: out = x + scale * (Y @ w2^T + b2), R5 pipeline + warp split ----
    const float scale = __ldg(scale_p);
    const float2* b2v = (const float2*)b2p;
    const float2* xg2 = (const float2*)xg;
    float2* outg2 = (float2*)(out + 64 * CDIM + (size_t)row0 * CDIM);
    const char* w2c = (const char*)g_w2t;

    // warp split: mg = w&3 -> rows mg*32..+31 (2 m-tiles of 16), ng = w>>2 -> cols ng*32..+31
    const int mg = w & 3, ng = w >> 2;
    const uint32_t aP3_base = xs_u + (mg * 32 + ((p & 1) << 3) + lr) * XS_ROWB + ((p >> 1) << 4);

    if (tid == 0) bulk_load(s_u, w2c, W2_CH_B, mb_u + 32);   // buf0 free (phase2 nc=10 synced)
    float acc3[2][4][4];
    for (int st = 0; st < 144; st++) {
        int nc = st / 12, kc = st % 12;
        if (kc == 0) {
#pragma unroll
            for (int mt = 0; mt < 2; mt++)
#pragma unroll
                for (int nt = 0; nt < 4; nt++)
#pragma unroll
                    for (int j = 0; j < 4; j++) acc3[mt][nt][j] = 0.f;
        }
        __syncthreads();
        if (tid == 0 && st < 143)
            bulk_load(s_u + ((st + 1) & 1) * STAGE_B, w2c + (size_t)(st + 1) * W2_CH_B,
                      W2_CH_B, mb_u + 32 + ((st + 1) & 1) * 8);
        mbar_wait(mb_u + 32 + (st & 1) * 8, (st >> 1) & 1);
        uint32_t bcur = s_u + (st & 1) * STAGE_B;
#pragma unroll
        for (int ks = 0; ks < 4; ks++) {
            uint32_t a[2][4], b[2][4];
#pragma unroll
            for (int mt = 0; mt < 2; mt++)
                ldsm_x4(a[mt][0], a[mt][1], a[mt][2], a[mt][3],
                        aP3_base + mt * 16 * XS_ROWB + kc * 128 + ks * 32);
#pragma unroll
            for (int pr = 0; pr < 2; pr++)
                ldsm_x4(b[pr][0], b[pr][1], b[pr][2], b[pr][3],
                        bcur + (ng * 32 + pr * 16 + bRow) * 128 + (((ks << 1) + bCol16) ^ lr) * 16);
#pragma unroll
            for (int mt = 0; mt < 2; mt++)
#pragma unroll
                for (int pr = 0; pr < 2; pr++) {
                    mma16816(acc3[mt][2 * pr], a[mt], b[pr]);
                    mma16816(acc3[mt][2 * pr + 1], a[mt], b[pr] + 2);
                }
        }
        if (kc == 11) {
            // epilogue: fp32 x re-read + scaled update (rows mg*32.., cols nc*64+ng*32..)
#pragma unroll
            for (int mt = 0; mt < 2; mt++)
#pragma unroll
                for (int nt = 0; nt < 4; nt++) {
                    int n = nc * 64 + ng * 32 + nt * 8 + tg * 2;
                    float2 bb = __ldg(&b2v[n >> 1]);
                    int r1 = mg * 32 + mt * 16 + g, r2 = r1 + 8;
                    float2 x1 = __ldg(&xg2[(size_t)r1 * (CDIM / 2) + (n >> 1)]);
                    float2 x2 = __ldg(&xg2[(size_t)r2 * (CDIM / 2) + (n >> 1)]);
                    float2 o1, o2;
                    o1.x = x1.x + scale * (acc3[mt][nt][0] + bb.x);
                    o1.y = x1.y + scale * (acc3[mt][nt][1] + bb.y);
                    o2.x = x2.x + scale * (acc3[mt][nt][2] + bb.x);
                    o2.y = x2.y + scale * (acc3[mt][nt][3] + bb.y);
                    outg2[(size_t)r1 * (CDIM / 2) + (n >> 1)] = o1;
                    outg2[(size_t)r2 * (CDIM / 2) + (n >> 1)] = o2;
                }
        }
    }
}

// ---------------- launch ----------------

extern "C" void kernel_launch(void* const* d_in, const int* in_sizes, int n_in,
                              void* d_out, int out_size) {
    (void)in_sizes; (void)n_in; (void)out_size;
    const float* feats = (const float*)d_in[0];
    const float* ta    = (const float*)d_in[1];
    const float* tb    = (const float*)d_in[2];
    const float* scale = (const float*)d_in[3];
    const float* w1    = (const float*)d_in[4];
    const float* b1    = (const float*)d_in[5];
    const float* w2    = (const float*)d_in[6];
    const float* b2    = (const float*)d_in[7];
    const int*   layer = (const int*)d_in[8];
    float* out = (float*)d_out;

    prep_tokens<<<(MTOK * CDIM + 255) / 256, 256>>>(ta, tb, layer);
    prep_t1<<<CDIM / T1_CBLK, 128>>>(w1, b1);
    prep_w2<<<(CDIM * CDIM / 8 + 255) / 256, 256>>>(w2);
    copy_cls<<<(64 * CDIM / 4 + 255) / 256, 256>>>(feats, out);

    static bool attr_set = false;
    if (!attr_set) {
        cudaFuncSetAttribute(lst_main, cudaFuncAttributeMaxDynamicSharedMemorySize, SMEM_BYTES);
        attr_set = true;
    }
    lst_main<<<65536 / MTILE, 256, SMEM_BYTES>>>(feats, b2, scale, out);
}

// round 15
// speedup vs baseline: 1.7578x; 1.1431x over previous
#include <cuda_runtime.h>
#include <cuda_bf16.h>
#include <cstdint>

#define CDIM 768
#define MTOK 104
#define MT_REAL 100
#define MTILE 128
#define XS_STRIDE 776          // bf16 per Xs row (768+8 pad)
#define XS_ROWB 1552
#define XS_SZ (MTILE*XS_ROWB)  // 198656
#define STAGE_B 16384
#define MB_OFF (XS_SZ + 2*STAGE_B)   // 231424
#define SMEM_BYTES (MB_OFF + 64)     // 231488
#define TOK_CH_B (MTOK*128)    // 13312
#define T1_CH_B  (64*256)      // 16384
#define W2_CH_B  16384         // two 64x64 k-blocks per step

__device__ __align__(16) float g_tokens[MT_REAL * CDIM];
__device__ __align__(16) __nv_bfloat16 g_tok_t[12 * MTOK * 64];   // swizzled k-blocks
__device__ __align__(16) __nv_bfloat16 g_t1t[12 * 64 * 128];      // swizzled
__device__ __align__(16) __nv_bfloat16 g_w2t[144 * 64 * 64];      // swizzled 8KB blocks

__device__ __forceinline__ uint32_t pack_bf2(float a, float b) {
    __nv_bfloat162 h = __floats2bfloat162_rn(a, b);
    return *reinterpret_cast<uint32_t*>(&h);
}
__device__ __forceinline__ void mma16816(float* d, const uint32_t* a, const uint32_t* b) {
    asm volatile(
        "mma.sync.aligned.m16n8k16.row.col.f32.bf16.bf16.f32 "
        "{%0,%1,%2,%3}, {%4,%5,%6,%7}, {%8,%9}, {%0,%1,%2,%3};"
        : "+f"(d[0]), "+f"(d[1]), "+f"(d[2]), "+f"(d[3])
        : "r"(a[0]), "r"(a[1]), "r"(a[2]), "r"(a[3]), "r"(b[0]), "r"(b[1]));
}
__device__ __forceinline__ void ldsm_x4(uint32_t& r0, uint32_t& r1, uint32_t& r2, uint32_t& r3,
                                        uint32_t addr) {
    asm volatile("ldmatrix.sync.aligned.m8n8.x4.shared.b16 {%0,%1,%2,%3}, [%4];"
                 : "=r"(r0), "=r"(r1), "=r"(r2), "=r"(r3) : "r"(addr));
}
__device__ __forceinline__ void ldsm_x2(uint32_t& r0, uint32_t& r1, uint32_t addr) {
    asm volatile("ldmatrix.sync.aligned.m8n8.x2.shared.b16 {%0,%1}, [%2];"
                 : "=r"(r0), "=r"(r1) : "r"(addr));
}
__device__ __forceinline__ void mbar_init(uint32_t mbar, uint32_t cnt) {
    asm volatile("mbarrier.init.shared.b64 [%0], %1;" :: "r"(mbar), "r"(cnt) : "memory");
}
__device__ __forceinline__ void bulk_load(uint32_t dst, const void* src, uint32_t bytes,
                                          uint32_t mbar) {
    asm volatile("mbarrier.arrive.expect_tx.shared.b64 _, [%0], %1;"
                 :: "r"(mbar), "r"(bytes) : "memory");
    asm volatile("cp.async.bulk.shared::cta.global.mbarrier::complete_tx::bytes "
                 "[%0], [%1], %2, [%3];"
                 :: "r"(dst), "l"(src), "r"(bytes), "r"(mbar) : "memory");
}
__device__ __forceinline__ void mbar_wait(uint32_t mbar, uint32_t parity) {
    asm volatile(
        "{\n\t"
        ".reg .pred P1;\n\t"
        "LAB_WAIT_%=:\n\t"
        "mbarrier.try_wait.parity.acquire.cta.shared::cta.b64 P1, [%0], %1, 0x989680;\n\t"
        "@P1 bra LAB_DONE_%=;\n\t"
        "bra LAB_WAIT_%=;\n\t"
        "LAB_DONE_%=:\n\t"
        "}" :: "r"(mbar), "r"(parity) : "memory");
}

// ---------------- prep kernels ----------------

__global__ void prep_tokens(const float* __restrict__ ta, const float* __restrict__ tb,
                            const int* __restrict__ layer_p) {
    int L = __ldg(layer_p);
    int i = blockIdx.x * 256 + threadIdx.x;
    if (i >= MTOK * CDIM) return;
    int m = i / CDIM, c = i % CDIM;
    float acc = 0.f;
    if (m < MT_REAL) {
        const float* a = ta + (size_t)L * MT_REAL * 32 + m * 32;
        const float* b = tb + (size_t)L * 32 * CDIM + c;
#pragma unroll
        for (int k = 0; k < 32; k++) acc += __ldg(a + k) * __ldg(b + k * CDIM);
        g_tokens[m * CDIM + c] = acc;
    }
    int kc = c >> 6, s = (c >> 3) & 7, e = c & 7;
    g_tok_t[((kc * MTOK + m) << 6) + ((s ^ (m & 7)) << 3) + e] = __float2bfloat16(acc);
}

#define T1_CBLK 8
__global__ void prep_t1(const float* __restrict__ w1, const float* __restrict__ b1) {
    __shared__ float w1s[T1_CBLK][CDIM];
    int c0 = blockIdx.x * T1_CBLK;
    for (int i = threadIdx.x; i < T1_CBLK * CDIM; i += blockDim.x)
        w1s[i / CDIM][i % CDIM] = __ldg(&w1[(size_t)(c0 + i / CDIM) * CDIM + (i % CDIM)]);
    __syncthreads();
    int m = threadIdx.x;
    float acc[T1_CBLK];
#pragma unroll
    for (int j = 0; j < T1_CBLK; j++) acc[j] = 0.f;
    bool live = (m >= 1 && m < MT_REAL);
    if (live) {
        const float* tok = g_tokens + (size_t)m * CDIM;
#pragma unroll 4
        for (int k = 0; k < CDIM; k++) {
            float tv = tok[k];
#pragma unroll
            for (int j = 0; j < T1_CBLK; j++) acc[j] += tv * w1s[j][k];
        }
    }
#pragma unroll
    for (int j = 0; j < T1_CBLK; j++) {
        float v = live ? (acc[j] + __ldg(b1 + c0 + j)) : 0.f;
        int c = c0 + j, nc = c >> 6, rr = c & 63;
        int off = ((nc * 64 + rr) << 7) + ((m >> 6) << 6) + ((((m >> 3) & 7) ^ (rr & 7)) << 3) + (m & 7);
        g_t1t[off] = __float2bfloat16(v);
    }
}

__global__ void prep_w2(const float* __restrict__ w2) {
    int i = blockIdx.x * 256 + threadIdx.x;
    if (i >= CDIM * CDIM / 8) return;
    int r = i / 96, cu = i % 96, c0 = cu * 8;
    const float4* v = (const float4*)(w2 + (size_t)r * CDIM + c0);
    float4 v0 = __ldg(v), v1 = __ldg(v + 1);
    uint32_t u[4];
    u[0] = pack_bf2(v0.x, v0.y); u[1] = pack_bf2(v0.z, v0.w);
    u[2] = pack_bf2(v1.x, v1.y); u[3] = pack_bf2(v1.z, v1.w);
    int nc = r >> 6, rr = r & 63, kcb = c0 >> 6, s = (c0 >> 3) & 7;
    int off = (((nc * 12 + kcb) * 64 + rr) << 6) + ((s ^ (rr & 7)) << 3);
    *(uint4*)(g_w2t + off) = *(uint4*)u;
}

__global__ void copy_cls(const float* __restrict__ feats, float* __restrict__ out) {
    int i = blockIdx.x * 256 + threadIdx.x;
    if (i < 64 * CDIM / 4) ((float4*)out)[i] = ((const float4*)feats)[i];
}

// ---------------- fused main kernel ----------------

__global__ __launch_bounds__(256, 1) void lst_main(
    const float* __restrict__ feats, const float* __restrict__ b2p,
    const float* __restrict__ scale_p, float* __restrict__ out) {
    extern __shared__ __align__(16) char smem_raw[];
    uint32_t* Xu = (uint32_t*)smem_raw;

    const uint32_t xs_u = (uint32_t)__cvta_generic_to_shared(smem_raw);
    const uint32_t s_u = xs_u + XS_SZ;
    const uint32_t mb_u = xs_u + MB_OFF;

    const int tid = threadIdx.x;
    const int w = tid >> 5, lane = tid & 31;
    const int g = lane >> 2, tg = lane & 3;
    const int wr0 = w * 16;
    const int p = lane >> 3, lr = lane & 7;
    const int row0 = blockIdx.x * MTILE;
    const float* xg = feats + 64 * CDIM + (size_t)row0 * CDIM;

    const uint32_t aA_base = xs_u + (wr0 + ((p & 1) << 3) + lr) * XS_ROWB + ((p >> 1) << 4);
    const int bRow = ((p >> 1) << 3) + lr;
    const int bCol16 = p & 1;

    if (tid == 0) {
#pragma unroll
        for (int i = 0; i < 6; i++) mbar_init(mb_u + i * 8, 1);
    }
    __syncthreads();

    // prologue: tokens chunk 0 -> buf0
    if (tid == 0) bulk_load(s_u, g_tok_t, TOK_CH_B, mb_u + 0);

    // ---- Phase 0: x tile -> bf16 smem ----
    for (int i = tid; i < MTILE * (CDIM / 4); i += 256) {
        int r = i / (CDIM / 4);
        int c4 = i % (CDIM / 4);
        float4 v = __ldg(&((const float4*)xg)[(size_t)r * (CDIM / 4) + c4]);
        Xu[r * (XS_STRIDE / 2) + c4 * 2] = pack_bf2(v.x, v.y);
        Xu[r * (XS_STRIDE / 2) + c4 * 2 + 1] = pack_bf2(v.z, v.w);
    }

    // ---- Phase 1: GEMM1 logits = X @ tokens^T ----
    float acc1[13][4];
#pragma unroll
    for (int t = 0; t < 13; t++)
#pragma unroll
        for (int j = 0; j < 4; j++) acc1[t][j] = 0.f;

    for (int kc = 0; kc < 12; kc++) {
        __syncthreads();
        if (tid == 0 && kc < 11)
            bulk_load(s_u + ((kc + 1) & 1) * STAGE_B, (const char*)g_tok_t + (kc + 1) * TOK_CH_B,
                      TOK_CH_B, mb_u + ((kc + 1) & 1) * 8);
        mbar_wait(mb_u + (kc & 1) * 8, (kc >> 1) & 1);
        uint32_t tcur = s_u + (kc & 1) * STAGE_B;
#pragma unroll
        for (int ks = 0; ks < 4; ks++) {
            uint32_t a[4];
            ldsm_x4(a[0], a[1], a[2], a[3], aA_base + kc * 128 + ks * 32);
#pragma unroll
            for (int tp = 0; tp < 6; tp++) {
                uint32_t b[4];
                ldsm_x4(b[0], b[1], b[2], b[3],
                        tcur + (tp * 16 + bRow) * 128 + (((ks << 1) + bCol16) ^ lr) * 16);
                mma16816(acc1[2 * tp], a, b);
                mma16816(acc1[2 * tp + 1], a, b + 2);
            }
            {
                uint32_t b0, b1v;
                uint32_t addr = tcur + (96 + lr) * 128 + (((ks << 1) + ((lane >> 3) & 1)) ^ lr) * 16;
                ldsm_x2(b0, b1v, addr);
                uint32_t bb[2] = {b0, b1v};
                mma16816(acc1[12], a, bb);
            }
        }
    }

    // ---- Phase 1.5: softmax in registers ----
    const float rsc = 0.03608439182435161f;
    float mx0 = -1e30f, mx1 = -1e30f;
#pragma unroll
    for (int t = 0; t < 13; t++)
#pragma unroll
        for (int j = 0; j < 4; j++) {
            int m = t * 8 + tg * 2 + (j & 1);
            float v = acc1[t][j] * rsc;
            acc1[t][j] = v;
            if (m < MT_REAL) { if (j < 2) mx0 = fmaxf(mx0, v); else mx1 = fmaxf(mx1, v); }
        }
    mx0 = fmaxf(mx0, __shfl_xor_sync(0xffffffffu, mx0, 1));
    mx0 = fmaxf(mx0, __shfl_xor_sync(0xffffffffu, mx0, 2));
    mx1 = fmaxf(mx1, __shfl_xor_sync(0xffffffffu, mx1, 1));
    mx1 = fmaxf(mx1, __shfl_xor_sync(0xffffffffu, mx1, 2));
    float s0 = 0.f, s1 = 0.f;
#pragma unroll
    for (int t = 0; t < 13; t++)
#pragma unroll
        for (int j = 0; j < 4; j++) {
            int m = t * 8 + tg * 2 + (j & 1);
            float e = (m < MT_REAL) ? __expf(acc1[t][j] - ((j < 2) ? mx0 : mx1)) : 0.f;
            acc1[t][j] = e;
            if (j < 2) s0 += e; else s1 += e;
        }
    s0 += __shfl_xor_sync(0xffffffffu, s0, 1);
    s0 += __shfl_xor_sync(0xffffffffu, s0, 2);
    s1 += __shfl_xor_sync(0xffffffffu, s1, 1);
    s1 += __shfl_xor_sync(0xffffffffu, s1, 2);
    float inv0 = 1.f / s0, inv1 = 1.f / s1;
    if (tg == 0) { acc1[0][0] = 0.f; acc1[0][2] = 0.f; }

    uint32_t pa[7][4];
#pragma unroll
    for (int q = 0; q < 7; q++) {
        int t0 = 2 * q;
        pa[q][0] = pack_bf2(acc1[t0][0] * inv0, acc1[t0][1] * inv0);
        pa[q][1] = pack_bf2(acc1[t0][2] * inv1, acc1[t0][3] * inv1);
        if (t0 + 1 < 13) {
            pa[q][2] = pack_bf2(acc1[t0 + 1][0] * inv0, acc1[t0 + 1][1] * inv0);
            pa[q][3] = pack_bf2(acc1[t0 + 1][2] * inv1, acc1[t0 + 1][3] * inv1);
        } else { pa[q][2] = 0u; pa[q][3] = 0u; }
    }

    // ---- Phase 2: delta1 = P @ t1full, y = x + delta1 (in place over Xs) ----
    if (tid == 0) bulk_load(s_u, g_t1t, T1_CH_B, mb_u + 16);
    for (int nc = 0; nc < 12; nc++) {
        __syncthreads();
        if (tid == 0 && nc < 11)
            bulk_load(s_u + ((nc + 1) & 1) * STAGE_B, (const char*)g_t1t + (nc + 1) * T1_CH_B,
                      T1_CH_B, mb_u + 16 + ((nc + 1) & 1) * 8);
        mbar_wait(mb_u + 16 + (nc & 1) * 8, (nc >> 1) & 1);
        uint32_t scur = s_u + (nc & 1) * STAGE_B;
        float acc2[8][4];
#pragma unroll
        for (int t = 0; t < 8; t++)
#pragma unroll
            for (int j = 0; j < 4; j++) acc2[t][j] = 0.f;
#pragma unroll
        for (int q = 0; q < 7; q++) {
            int u2 = 2 * q + bCol16;
#pragma unroll
            for (int tp = 0; tp < 4; tp++) {
                uint32_t b[4];
                ldsm_x4(b[0], b[1], b[2], b[3],
                        scur + (tp * 16 + bRow) * 256 + (u2 >> 3) * 128 + ((u2 & 7) ^ lr) * 16);
                mma16816(acc2[2 * tp], pa[q], b);
                mma16816(acc2[2 * tp + 1], pa[q], b + 2);
            }
        }
#pragma unroll
        for (int t = 0; t < 8; t++) {
            int c0 = nc * 64 + t * 8 + tg * 2;
            uint32_t* p0 = &Xu[(wr0 + g) * (XS_STRIDE / 2) + c0 / 2];
            uint32_t* p1 = &Xu[(wr0 + g + 8) * (XS_STRIDE / 2) + c0 / 2];
            __nv_bfloat162 x0 = *(__nv_bfloat162*)p0;
            __nv_bfloat162 x1 = *(__nv_bfloat162*)p1;
            *p0 = pack_bf2(__bfloat162float(x0.x) + acc2[t][0],
                           __bfloat162float(x0.y) + acc2[t][1]);
            *p1 = pack_bf2(__bfloat162float(x1.x) + acc2[t][2],
                           __bfloat162float(x1.y) + acc2[t][3]);
        }
    }

    // ---- Phase 3: out = x + scale*(Y @ w2^T + b2), 72 steps x 16KB, R5 ping-pong ----
    const float scale = __ldg(scale_p);
    const float2* b2v = (const float2*)b2p;
    const float2* xg2 = (const float2*)xg;
    float2* outg2 = (float2*)(out + 64 * CDIM + (size_t)row0 * CDIM);
    const char* w2c = (const char*)g_w2t;

    // warp split: mg = w&3 -> rows mg*32..+31 (2 m-tiles of 16), ng = w>>2 -> cols ng*32..+31
    const int mg = w & 3, ng = w >> 2;
    const uint32_t aP3_base = xs_u + (mg * 32 + ((p & 1) << 3) + lr) * XS_ROWB + ((p >> 1) << 4);

    if (tid == 0) bulk_load(s_u, w2c, W2_CH_B, mb_u + 32);   // buf0 free (phase2 nc=10 synced)
    float acc3[2][4][4];
    for (int st = 0; st < 72; st++) {
        int nc = st / 6, kp = st % 6;
        if (kp == 0) {
#pragma unroll
            for (int mt = 0; mt < 2; mt++)
#pragma unroll
                for (int nt = 0; nt < 4; nt++)
#pragma unroll
                    for (int j = 0; j < 4; j++) acc3[mt][nt][j] = 0.f;
        }
        __syncthreads();
        if (tid == 0 && st < 71)
            bulk_load(s_u + ((st + 1) & 1) * STAGE_B, w2c + (size_t)(st + 1) * W2_CH_B,
                      W2_CH_B, mb_u + 32 + ((st + 1) & 1) * 8);
        mbar_wait(mb_u + 32 + (st & 1) * 8, (st >> 1) & 1);
        uint32_t bcur = s_u + (st & 1) * STAGE_B;
#pragma unroll
        for (int kb = 0; kb < 2; kb++) {
            int kc = kp * 2 + kb;
            uint32_t bblk = bcur + kb * 8192;
#pragma unroll
            for (int ks = 0; ks < 4; ks++) {
                uint32_t a[2][4], b[2][4];
#pragma unroll
                for (int mt = 0; mt < 2; mt++)
                    ldsm_x4(a[mt][0], a[mt][1], a[mt][2], a[mt][3],
                            aP3_base + mt * 16 * XS_ROWB + kc * 128 + ks * 32);
#pragma unroll
                for (int pr = 0; pr < 2; pr++)
                    ldsm_x4(b[pr][0], b[pr][1], b[pr][2], b[pr][3],
                            bblk + (ng * 32 + pr * 16 + bRow) * 128 + (((ks << 1) + bCol16) ^ lr) * 16);
#pragma unroll
                for (int mt = 0; mt < 2; mt++)
#pragma unroll
                    for (int pr = 0; pr < 2; pr++) {
                        mma16816(acc3[mt][2 * pr], a[mt], b[pr]);
                        mma16816(acc3[mt][2 * pr + 1], a[mt], b[pr] + 2);
                    }
            }
        }
        if (kp == 5) {
            // epilogue: fp32 x re-read + scaled update (rows mg*32.., cols nc*64+ng*32..)
#pragma unroll
            for (int mt = 0; mt < 2; mt++)
#pragma unroll
                for (int nt = 0; nt < 4; nt++) {
                    int n = nc * 64 + ng * 32 + nt * 8 + tg * 2;
                    float2 bb = __ldg(&b2v[n >> 1]);
                    int r1 = mg * 32 + mt * 16 + g, r2 = r1 + 8;
                    float2 x1 = __ldg(&xg2[(size_t)r1 * (CDIM / 2) + (n >> 1)]);
                    float2 x2 = __ldg(&xg2[(size_t)r2 * (CDIM / 2) + (n >> 1)]);
                    float2 o1, o2;
                    o1.x = x1.x + scale * (acc3[mt][nt][0] + bb.x);
                    o1.y = x1.y + scale * (acc3[mt][nt][1] + bb.y);
                    o2.x = x2.x + scale * (acc3[mt][nt][2] + bb.x);
                    o2.y = x2.y + scale * (acc3[mt][nt][3] + bb.y);
                    outg2[(size_t)r1 * (CDIM / 2) + (n >> 1)] = o1;
                    outg2[(size_t)r2 * (CDIM / 2) + (n >> 1)] = o2;
                }
        }
    }
}

// ---------------- launch ----------------

extern "C" void kernel_launch(void* const* d_in, const int* in_sizes, int n_in,
                              void* d_out, int out_size) {
    (void)in_sizes; (void)n_in; (void)out_size;
    const float* feats = (const float*)d_in[0];
    const float* ta    = (const float*)d_in[1];
    const float* tb    = (const float*)d_in[2];
    const float* scale = (const float*)d_in[3];
    const float* w1    = (const float*)d_in[4];
    const float* b1    = (const float*)d_in[5];
    const float* w2    = (const float*)d_in[6];
    const float* b2    = (const float*)d_in[7];
    const int*   layer = (const int*)d_in[8];
    float* out = (float*)d_out;

    prep_tokens<<<(MTOK * CDIM + 255) / 256, 256>>>(ta, tb, layer);
    prep_t1<<<CDIM / T1_CBLK, 128>>>(w1, b1);
    prep_w2<<<(CDIM * CDIM / 8 + 255) / 256, 256>>>(w2);
    copy_cls<<<(64 * CDIM / 4 + 255) / 256, 256>>>(feats, out);

    static bool attr_set = false;
    if (!attr_set) {
        cudaFuncSetAttribute(lst_main, cudaFuncAttributeMaxDynamicSharedMemorySize, SMEM_BYTES);
        attr_set = true;
    }
    lst_main<<<65536 / MTILE, 256, SMEM_BYTES>>>(feats, b2, scale, out);
}

// round 16
// speedup vs baseline: 1.7591x; 1.0008x over previous
#include <cuda_runtime.h>
#include <cuda_bf16.h>
#include <cstdint>

#define CDIM 768
#define MTOK 104
#define MT_REAL 100
#define MTILE 112              // rows per CTA (last tile: 16)
#define NTILES 586
#define XS_STRIDE 776          // bf16 per Xs row (768+8 pad)
#define XS_ROWB 1552
#define XS_SZ (128*XS_ROWB)    // keep layout capacity at 128 rows
#define STAGE_B 16384
#define MB_OFF (XS_SZ + 2*STAGE_B)   // 231424
#define SMEM_BYTES (MB_OFF + 64)     // 231488
#define TOK_CH_B (MTOK*128)    // 13312
#define T1_CH_B  (64*256)      // 16384
#define W2_CH_B  16384         // two 64x64 k-blocks per step

__device__ __align__(16) float g_tokens[MT_REAL * CDIM];
__device__ __align__(16) __nv_bfloat16 g_tok_t[12 * MTOK * 64];   // swizzled k-blocks
__device__ __align__(16) __nv_bfloat16 g_t1t[12 * 64 * 128];      // swizzled
__device__ __align__(16) __nv_bfloat16 g_w2t[144 * 64 * 64];      // swizzled 8KB blocks

__device__ __forceinline__ uint32_t pack_bf2(float a, float b) {
    __nv_bfloat162 h = __floats2bfloat162_rn(a, b);
    return *reinterpret_cast<uint32_t*>(&h);
}
__device__ __forceinline__ void mma16816(float* d, const uint32_t* a, const uint32_t* b) {
    asm volatile(
        "mma.sync.aligned.m16n8k16.row.col.f32.bf16.bf16.f32 "
        "{%0,%1,%2,%3}, {%4,%5,%6,%7}, {%8,%9}, {%0,%1,%2,%3};"
        : "+f"(d[0]), "+f"(d[1]), "+f"(d[2]), "+f"(d[3])
        : "r"(a[0]), "r"(a[1]), "r"(a[2]), "r"(a[3]), "r"(b[0]), "r"(b[1]));
}
__device__ __forceinline__ void ldsm_x4(uint32_t& r0, uint32_t& r1, uint32_t& r2, uint32_t& r3,
                                        uint32_t addr) {
    asm volatile("ldmatrix.sync.aligned.m8n8.x4.shared.b16 {%0,%1,%2,%3}, [%4];"
                 : "=r"(r0), "=r"(r1), "=r"(r2), "=r"(r3) : "r"(addr));
}
__device__ __forceinline__ void ldsm_x2(uint32_t& r0, uint32_t& r1, uint32_t addr) {
    asm volatile("ldmatrix.sync.aligned.m8n8.x2.shared.b16 {%0,%1}, [%2];"
                 : "=r"(r0), "=r"(r1) : "r"(addr));
}
__device__ __forceinline__ void mbar_init(uint32_t mbar, uint32_t cnt) {
    asm volatile("mbarrier.init.shared.b64 [%0], %1;" :: "r"(mbar), "r"(cnt) : "memory");
}
__device__ __forceinline__ void bulk_load(uint32_t dst, const void* src, uint32_t bytes,
                                          uint32_t mbar) {
    asm volatile("mbarrier.arrive.expect_tx.shared.b64 _, [%0], %1;"
                 :: "r"(mbar), "r"(bytes) : "memory");
    asm volatile("cp.async.bulk.shared::cta.global.mbarrier::complete_tx::bytes "
                 "[%0], [%1], %2, [%3];"
                 :: "r"(dst), "l"(src), "r"(bytes), "r"(mbar) : "memory");
}
__device__ __forceinline__ void mbar_wait(uint32_t mbar, uint32_t parity) {
    asm volatile(
        "{\n\t"
        ".reg .pred P1;\n\t"
        "LAB_WAIT_%=:\n\t"
        "mbarrier.try_wait.parity.acquire.cta.shared::cta.b64 P1, [%0], %1, 0x989680;\n\t"
        "@P1 bra LAB_DONE_%=;\n\t"
        "bra LAB_WAIT_%=;\n\t"
        "LAB_DONE_%=:\n\t"
        "}" :: "r"(mbar), "r"(parity) : "memory");
}

// ---------------- prep kernels ----------------

__global__ void prep_tokens(const float* __restrict__ ta, const float* __restrict__ tb,
                            const int* __restrict__ layer_p) {
    int L = __ldg(layer_p);
    int i = blockIdx.x * 256 + threadIdx.x;
    if (i >= MTOK * CDIM) return;
    int m = i / CDIM, c = i % CDIM;
    float acc = 0.f;
    if (m < MT_REAL) {
        const float* a = ta + (size_t)L * MT_REAL * 32 + m * 32;
        const float* b = tb + (size_t)L * 32 * CDIM + c;
#pragma unroll
        for (int k = 0; k < 32; k++) acc += __ldg(a + k) * __ldg(b + k * CDIM);
        g_tokens[m * CDIM + c] = acc;
    }
    int kc = c >> 6, s = (c >> 3) & 7, e = c & 7;
    g_tok_t[((kc * MTOK + m) << 6) + ((s ^ (m & 7)) << 3) + e] = __float2bfloat16(acc);
}

#define T1_CBLK 8
__global__ void prep_t1(const float* __restrict__ w1, const float* __restrict__ b1) {
    __shared__ float w1s[T1_CBLK][CDIM];
    int c0 = blockIdx.x * T1_CBLK;
    for (int i = threadIdx.x; i < T1_CBLK * CDIM; i += blockDim.x)
        w1s[i / CDIM][i % CDIM] = __ldg(&w1[(size_t)(c0 + i / CDIM) * CDIM + (i % CDIM)]);
    __syncthreads();
    int m = threadIdx.x;
    float acc[T1_CBLK];
#pragma unroll
    for (int j = 0; j < T1_CBLK; j++) acc[j] = 0.f;
    bool live = (m >= 1 && m < MT_REAL);
    if (live) {
        const float* tok = g_tokens + (size_t)m * CDIM;
#pragma unroll 4
        for (int k = 0; k < CDIM; k++) {
            float tv = tok[k];
#pragma unroll
            for (int j = 0; j < T1_CBLK; j++) acc[j] += tv * w1s[j][k];
        }
    }
#pragma unroll
    for (int j = 0; j < T1_CBLK; j++) {
        float v = live ? (acc[j] + __ldg(b1 + c0 + j)) : 0.f;
        int c = c0 + j, nc = c >> 6, rr = c & 63;
        int off = ((nc * 64 + rr) << 7) + ((m >> 6) << 6) + ((((m >> 3) & 7) ^ (rr & 7)) << 3) + (m & 7);
        g_t1t[off] = __float2bfloat16(v);
    }
}

__global__ void prep_w2(const float* __restrict__ w2) {
    int i = blockIdx.x * 256 + threadIdx.x;
    if (i >= CDIM * CDIM / 8) return;
    int r = i / 96, cu = i % 96, c0 = cu * 8;
    const float4* v = (const float4*)(w2 + (size_t)r * CDIM + c0);
    float4 v0 = __ldg(v), v1 = __ldg(v + 1);
    uint32_t u[4];
    u[0] = pack_bf2(v0.x, v0.y); u[1] = pack_bf2(v0.z, v0.w);
    u[2] = pack_bf2(v1.x, v1.y); u[3] = pack_bf2(v1.z, v1.w);
    int nc = r >> 6, rr = r & 63, kcb = c0 >> 6, s = (c0 >> 3) & 7;
    int off = (((nc * 12 + kcb) * 64 + rr) << 6) + ((s ^ (rr & 7)) << 3);
    *(uint4*)(g_w2t + off) = *(uint4*)u;
}

__global__ void copy_cls(const float* __restrict__ feats, float* __restrict__ out) {
    int i = blockIdx.x * 256 + threadIdx.x;
    if (i < 64 * CDIM / 4) ((float4*)out)[i] = ((const float4*)feats)[i];
}

// ---------------- fused main kernel ----------------

__global__ __launch_bounds__(256, 1) void lst_main(
    const float* __restrict__ feats, const float* __restrict__ b2p,
    const float* __restrict__ scale_p, float* __restrict__ out) {
    extern __shared__ __align__(16) char smem_raw[];
    uint32_t* Xu = (uint32_t*)smem_raw;

    const uint32_t xs_u = (uint32_t)__cvta_generic_to_shared(smem_raw);
    const uint32_t s_u = xs_u + XS_SZ;
    const uint32_t mb_u = xs_u + MB_OFF;

    const int tid = threadIdx.x;
    const int w = tid >> 5, lane = tid & 31;
    const int g = lane >> 2, tg = lane & 3;
    const int wr0 = w * 16;
    const int p = lane >> 3, lr = lane & 7;
    const int row0 = blockIdx.x * MTILE;
    const int M = min(MTILE, 65536 - row0);          // 112, or 16 for last tile
    const bool wlive = (wr0 < M);                    // warp has rows in phases 1/2
    const float* xg = feats + 64 * CDIM + (size_t)row0 * CDIM;

    const uint32_t aA_base = xs_u + (wr0 + ((p & 1) << 3) + lr) * XS_ROWB + ((p >> 1) << 4);
    const int bRow = ((p >> 1) << 3) + lr;
    const int bCol16 = p & 1;

    if (tid == 0) {
#pragma unroll
        for (int i = 0; i < 6; i++) mbar_init(mb_u + i * 8, 1);
    }
    __syncthreads();

    // prologue: tokens chunk 0 -> buf0
    if (tid == 0) bulk_load(s_u, g_tok_t, TOK_CH_B, mb_u + 0);

    // ---- Phase 0: x tile -> bf16 smem (rows < M only) ----
    for (int i = tid; i < M * (CDIM / 4); i += 256) {
        int r = i / (CDIM / 4);
        int c4 = i % (CDIM / 4);
        float4 v = __ldg(&((const float4*)xg)[(size_t)r * (CDIM / 4) + c4]);
        Xu[r * (XS_STRIDE / 2) + c4 * 2] = pack_bf2(v.x, v.y);
        Xu[r * (XS_STRIDE / 2) + c4 * 2 + 1] = pack_bf2(v.z, v.w);
    }

    // ---- Phase 1: GEMM1 logits = X @ tokens^T ----
    float acc1[13][4];
#pragma unroll
    for (int t = 0; t < 13; t++)
#pragma unroll
        for (int j = 0; j < 4; j++) acc1[t][j] = 0.f;

    for (int kc = 0; kc < 12; kc++) {
        __syncthreads();
        if (tid == 0 && kc < 11)
            bulk_load(s_u + ((kc + 1) & 1) * STAGE_B, (const char*)g_tok_t + (kc + 1) * TOK_CH_B,
                      TOK_CH_B, mb_u + ((kc + 1) & 1) * 8);
        mbar_wait(mb_u + (kc & 1) * 8, (kc >> 1) & 1);
        if (wlive) {
            uint32_t tcur = s_u + (kc & 1) * STAGE_B;
#pragma unroll
            for (int ks = 0; ks < 4; ks++) {
                uint32_t a[4];
                ldsm_x4(a[0], a[1], a[2], a[3], aA_base + kc * 128 + ks * 32);
#pragma unroll
                for (int tp = 0; tp < 6; tp++) {
                    uint32_t b[4];
                    ldsm_x4(b[0], b[1], b[2], b[3],
                            tcur + (tp * 16 + bRow) * 128 + (((ks << 1) + bCol16) ^ lr) * 16);
                    mma16816(acc1[2 * tp], a, b);
                    mma16816(acc1[2 * tp + 1], a, b + 2);
                }
                {
                    uint32_t b0, b1v;
                    uint32_t addr = tcur + (96 + lr) * 128 + (((ks << 1) + ((lane >> 3) & 1)) ^ lr) * 16;
                    ldsm_x2(b0, b1v, addr);
                    uint32_t bb[2] = {b0, b1v};
                    mma16816(acc1[12], a, bb);
                }
            }
        }
    }

    // ---- Phase 1.5: softmax in registers ----
    const float rsc = 0.03608439182435161f;
    float mx0 = -1e30f, mx1 = -1e30f;
#pragma unroll
    for (int t = 0; t < 13; t++)
#pragma unroll
        for (int j = 0; j < 4; j++) {
            int m = t * 8 + tg * 2 + (j & 1);
            float v = acc1[t][j] * rsc;
            acc1[t][j] = v;
            if (m < MT_REAL) { if (j < 2) mx0 = fmaxf(mx0, v); else mx1 = fmaxf(mx1, v); }
        }
    mx0 = fmaxf(mx0, __shfl_xor_sync(0xffffffffu, mx0, 1));
    mx0 = fmaxf(mx0, __shfl_xor_sync(0xffffffffu, mx0, 2));
    mx1 = fmaxf(mx1, __shfl_xor_sync(0xffffffffu, mx1, 1));
    mx1 = fmaxf(mx1, __shfl_xor_sync(0xffffffffu, mx1, 2));
    float s0 = 0.f, s1 = 0.f;
#pragma unroll
    for (int t = 0; t < 13; t++)
#pragma unroll
        for (int j = 0; j < 4; j++) {
            int m = t * 8 + tg * 2 + (j & 1);
            float e = (m < MT_REAL) ? __expf(acc1[t][j] - ((j < 2) ? mx0 : mx1)) : 0.f;
            acc1[t][j] = e;
            if (j < 2) s0 += e; else s1 += e;
        }
    s0 += __shfl_xor_sync(0xffffffffu, s0, 1);
    s0 += __shfl_xor_sync(0xffffffffu, s0, 2);
    s1 += __shfl_xor_sync(0xffffffffu, s1, 1);
    s1 += __shfl_xor_sync(0xffffffffu, s1, 2);
    float inv0 = 1.f / s0, inv1 = 1.f / s1;
    if (tg == 0) { acc1[0][0] = 0.f; acc1[0][2] = 0.f; }

    uint32_t pa[7][4];
#pragma unroll
    for (int q = 0; q < 7; q++) {
        int t0 = 2 * q;
        pa[q][0] = pack_bf2(acc1[t0][0] * inv0, acc1[t0][1] * inv0);
        pa[q][1] = pack_bf2(acc1[t0][2] * inv1, acc1[t0][3] * inv1);
        if (t0 + 1 < 13) {
            pa[q][2] = pack_bf2(acc1[t0 + 1][0] * inv0, acc1[t0 + 1][1] * inv0);
            pa[q][3] = pack_bf2(acc1[t0 + 1][2] * inv1, acc1[t0 + 1][3] * inv1);
        } else { pa[q][2] = 0u; pa[q][3] = 0u; }
    }

    // ---- Phase 2: delta1 = P @ t1full, y = x + delta1 (in place over Xs) ----
    if (tid == 0) bulk_load(s_u, g_t1t, T1_CH_B, mb_u + 16);
    for (int nc = 0; nc < 12; nc++) {
        __syncthreads();
        if (tid == 0 && nc < 11)
            bulk_load(s_u + ((nc + 1) & 1) * STAGE_B, (const char*)g_t1t + (nc + 1) * T1_CH_B,
                      T1_CH_B, mb_u + 16 + ((nc + 1) & 1) * 8);
        mbar_wait(mb_u + 16 + (nc & 1) * 8, (nc >> 1) & 1);
        if (wlive) {
            uint32_t scur = s_u + (nc & 1) * STAGE_B;
            float acc2[8][4];
#pragma unroll
            for (int t = 0; t < 8; t++)
#pragma unroll
                for (int j = 0; j < 4; j++) acc2[t][j] = 0.f;
#pragma unroll
            for (int q = 0; q < 7; q++) {
                int u2 = 2 * q + bCol16;
#pragma unroll
                for (int tp = 0; tp < 4; tp++) {
                    uint32_t b[4];
                    ldsm_x4(b[0], b[1], b[2], b[3],
                            scur + (tp * 16 + bRow) * 256 + (u2 >> 3) * 128 + ((u2 & 7) ^ lr) * 16);
                    mma16816(acc2[2 * tp], pa[q], b);
                    mma16816(acc2[2 * tp + 1], pa[q], b + 2);
                }
            }
#pragma unroll
            for (int t = 0; t < 8; t++) {
                int c0 = nc * 64 + t * 8 + tg * 2;
                uint32_t* p0 = &Xu[(wr0 + g) * (XS_STRIDE / 2) + c0 / 2];
                uint32_t* p1 = &Xu[(wr0 + g + 8) * (XS_STRIDE / 2) + c0 / 2];
                __nv_bfloat162 x0 = *(__nv_bfloat162*)p0;
                __nv_bfloat162 x1 = *(__nv_bfloat162*)p1;
                *p0 = pack_bf2(__bfloat162float(x0.x) + acc2[t][0],
                               __bfloat162float(x0.y) + acc2[t][1]);
                *p1 = pack_bf2(__bfloat162float(x1.x) + acc2[t][2],
                               __bfloat162float(x1.y) + acc2[t][3]);
            }
        }
    }

    // ---- Phase 3: out = x + scale*(Y @ w2^T + b2), 72 steps x 16KB, R5 ping-pong ----
    const float scale = __ldg(scale_p);
    const float2* b2v = (const float2*)b2p;
    const float2* xg2 = (const float2*)xg;
    float2* outg2 = (float2*)(out + 64 * CDIM + (size_t)row0 * CDIM);
    const char* w2c = (const char*)g_w2t;

    // warp split: mg = w&3 -> rows mg*32..+31 (2 m-tiles of 16), ng = w>>2 -> cols ng*32..+31
    const int mg = w & 3, ng = w >> 2;
    const bool v0 = (mg * 32) < M;          // m-tile mt=0 valid
    const bool v1 = (mg * 32 + 16) < M;     // m-tile mt=1 valid
    const uint32_t aP3_base = xs_u + (mg * 32 + ((p & 1) << 3) + lr) * XS_ROWB + ((p >> 1) << 4);

    if (tid == 0) bulk_load(s_u, w2c, W2_CH_B, mb_u + 32);   // buf0 free (phase2 nc=10 synced)
    float acc3[2][4][4];
    for (int st = 0; st < 72; st++) {
        int nc = st / 6, kp = st % 6;
        if (kp == 0) {
#pragma unroll
            for (int mt = 0; mt < 2; mt++)
#pragma unroll
                for (int nt = 0; nt < 4; nt++)
#pragma unroll
                    for (int j = 0; j < 4; j++) acc3[mt][nt][j] = 0.f;
        }
        __syncthreads();
        if (tid == 0 && st < 71)
            bulk_load(s_u + ((st + 1) & 1) * STAGE_B, w2c + (size_t)(st + 1) * W2_CH_B,
                      W2_CH_B, mb_u + 32 + ((st + 1) & 1) * 8);
        mbar_wait(mb_u + 32 + (st & 1) * 8, (st >> 1) & 1);
        if (v0) {
            uint32_t bcur = s_u + (st & 1) * STAGE_B;
#pragma unroll
            for (int kb = 0; kb < 2; kb++) {
                int kc = kp * 2 + kb;
                uint32_t bblk = bcur + kb * 8192;
#pragma unroll
                for (int ks = 0; ks < 4; ks++) {
                    uint32_t a[2][4], b[2][4];
                    ldsm_x4(a[0][0], a[0][1], a[0][2], a[0][3],
                            aP3_base + kc * 128 + ks * 32);
                    if (v1)
                        ldsm_x4(a[1][0], a[1][1], a[1][2], a[1][3],
                                aP3_base + 16 * XS_ROWB + kc * 128 + ks * 32);
#pragma unroll
                    for (int pr = 0; pr < 2; pr++)
                        ldsm_x4(b[pr][0], b[pr][1], b[pr][2], b[pr][3],
                                bblk + (ng * 32 + pr * 16 + bRow) * 128 + (((ks << 1) + bCol16) ^ lr) * 16);
#pragma unroll
                    for (int pr = 0; pr < 2; pr++) {
                        mma16816(acc3[0][2 * pr], a[0], b[pr]);
                        mma16816(acc3[0][2 * pr + 1], a[0], b[pr] + 2);
                    }
                    if (v1) {
#pragma unroll
                        for (int pr = 0; pr < 2; pr++) {
                            mma16816(acc3[1][2 * pr], a[1], b[pr]);
                            mma16816(acc3[1][2 * pr + 1], a[1], b[pr] + 2);
                        }
                    }
                }
            }
        }
        if (kp == 5 && v0) {
            // epilogue: fp32 x re-read + scaled update (rows mg*32.., cols nc*64+ng*32..)
#pragma unroll
            for (int mt = 0; mt < 2; mt++) {
                if (mt == 1 && !v1) break;
#pragma unroll
                for (int nt = 0; nt < 4; nt++) {
                    int n = nc * 64 + ng * 32 + nt * 8 + tg * 2;
                    float2 bb = __ldg(&b2v[n >> 1]);
                    int r1 = mg * 32 + mt * 16 + g, r2 = r1 + 8;
                    float2 x1 = __ldg(&xg2[(size_t)r1 * (CDIM / 2) + (n >> 1)]);
                    float2 x2 = __ldg(&xg2[(size_t)r2 * (CDIM / 2) + (n >> 1)]);
                    float2 o1, o2;
                    o1.x = x1.x + scale * (acc3[mt][nt][0] + bb.x);
                    o1.y = x1.y + scale * (acc3[mt][nt][1] + bb.y);
                    o2.x = x2.x + scale * (acc3[mt][nt][2] + bb.x);
                    o2.y = x2.y + scale * (acc3[mt][nt][3] + bb.y);
                    outg2[(size_t)r1 * (CDIM / 2) + (n >> 1)] = o1;
                    outg2[(size_t)r2 * (CDIM / 2) + (n >> 1)] = o2;
                }
            }
        }
    }
}

// ---------------- launch ----------------

extern "C" void kernel_launch(void* const* d_in, const int* in_sizes, int n_in,
                              void* d_out, int out_size) {
    (void)in_sizes; (void)n_in; (void)out_size;
    const float* feats = (const float*)d_in[0];
    const float* ta    = (const float*)d_in[1];
    const float* tb    = (const float*)d_in[2];
    const float* scale = (const float*)d_in[3];
    const float* w1    = (const float*)d_in[4];
    const float* b1    = (const float*)d_in[5];
    const float* w2    = (const float*)d_in[6];
    const float* b2    = (const float*)d_in[7];
    const int*   layer = (const int*)d_in[8];
    float* out = (float*)d_out;

    prep_tokens<<<(MTOK * CDIM + 255) / 256, 256>>>(ta, tb, layer);
    prep_t1<<<CDIM / T1_CBLK, 128>>>(w1, b1);
    prep_w2<<<(CDIM * CDIM / 8 + 255) / 256, 256>>>(w2);
    copy_cls<<<(64 * CDIM / 4 + 255) / 256, 256>>>(feats, out);

    static bool attr_set = false;
    if (!attr_set) {
        cudaFuncSetAttribute(lst_main, cudaFuncAttributeMaxDynamicSharedMemorySize, SMEM_BYTES);
        attr_set = true;
    }
    lst_main<<<NTILES, 256, SMEM_BYTES>>>(feats, b2, scale, out);
}